// round 11
// baseline (speedup 1.0000x reference)
#include <cuda_runtime.h>
#include <cuda_fp16.h>
#include <cstdint>

#define RS   88                 // halves per smem row (176 B)
#define MB   16                 // rows per block
#define ASZH (MB * RS)          // halves per A buffer
#define SMEM_BYTES ((2 * ASZH + 256 * RS) * 2)   // 50688

// ---------------- scratch ----------------
__device__ float g_feat[2 * 32 * 2 * 64 * 55];   // [sub][b][7040]
__device__ float g_y1[64 * 3400];
__device__ float g_y2[64 * 1000];
__device__ float g_y3[64 * 512];
__device__ float g_part[16 * 64 * 3400];

__device__ __forceinline__ float tanh_f(float x) {
    float r; asm("tanh.approx.f32 %0, %1;" : "=f"(r) : "f"(x)); return r;
}
// pre-activation already scaled by 0.5 (folded into weights)
__device__ __forceinline__ float sigm_pre(float xhalf) {
    return fmaf(0.5f, tanh_f(xhalf), 0.5f);
}

__device__ __forceinline__ uint32_t smem_u32(const void* p) {
    uint32_t a;
    asm("{ .reg .u64 t; cvta.to.shared.u64 t, %1; cvt.u32.u64 %0, t; }" : "=r"(a) : "l"(p));
    return a;
}

#define MMA16816(d, a0, a1, a2, a3, b0, b1) \
    asm volatile("mma.sync.aligned.m16n8k16.row.col.f32.f16.f16.f32 " \
        "{%0,%1,%2,%3}, {%4,%5,%6,%7}, {%8,%9}, {%0,%1,%2,%3};" \
        : "+f"((d)[0]), "+f"((d)[1]), "+f"((d)[2]), "+f"((d)[3]) \
        : "r"(a0), "r"(a1), "r"(a2), "r"(a3), "r"(b0), "r"(b1))

// ---------------- tensor-core LSTM (HMMA, 3 blocks/SM) ----------------
// grid = 440: blk/220 = cell, rb = (blk%220)*16 (exact, no padding).
// Warp w owns B cols [32w,32w+32): col n -> gate (n>>3)&3, channel 8w + (n&7).
// Lane owns rows {lane>>2, +8}, channels {8w+(lane&3)*2, +1}; full gate quad in-lane.
__global__ __launch_bounds__(256, 3)
void lstm_mma(const float* __restrict__ x1, const float* __restrict__ x2,
              const float* __restrict__ wx1, const float* __restrict__ wh1,
              const float* __restrict__ bx1, const float* __restrict__ bh1,
              const float* __restrict__ wx2, const float* __restrict__ wh2,
              const float* __restrict__ bx2, const float* __restrict__ bh2,
              float* __restrict__ feat)
{
    extern __shared__ __align__(16) __half smem[];
    __half* A0 = smem;
    __half* A1 = smem + ASZH;
    __half* Bw = smem + 2 * ASZH;

    int tid = threadIdx.x, wid = tid >> 5, lane = tid & 31;
    int blk = blockIdx.x;
    int cell = blk / 220;
    int rb   = (blk % 220) * MB;             // row base within cell-space (always full)

    const float* wh = cell ? wh2 : wh1;
    const float* wx = cell ? wx2 : wx1;
    const float* bx = cell ? bx2 : bx1;
    const float* bh = cell ? bh2 : bh1;

    // ---- build B (fp16, 0.5-prescaled for sigmoid gates i,f,o) ----
    {
        int n  = tid;
        int w  = n >> 5, g = (n >> 3) & 3, cl = n & 7;
        int gc = g * 64 + 8 * w + cl;        // source gate column
        float s = (g == 3) ? 1.0f : 0.5f;
        __half* bp = Bw + n * RS;
#pragma unroll 8
        for (int k = 0; k < 64; k++) bp[k] = __float2half(wh[k * 256 + gc] * s);
        bp[64] = __float2half(wx[gc] * s);
        bp[65] = __float2half(wx[256 + gc] * s);
        bp[66] = __float2half((bx[gc] + bh[gc]) * s);
#pragma unroll
        for (int k = 67; k < RS; k++) bp[k] = __float2half(0.f);
    }
    // ---- zero A buffers ----
    for (int i = tid; i < (2 * ASZH * 2) / 16; i += 256)
        ((uint4*)smem)[i] = make_uint4(0, 0, 0, 0);
    __syncthreads();

    // per-row x pointer (threads 0..15 own row tid)
    const float* xrp = nullptr;
    if (tid < MB) {
        int ric = rb + tid;
        int sub = ric / 1760, rem = ric % 1760, b = rem / 55, p = rem % 55;
        xrp = (sub ? x2 : x1) + (size_t)b * 256 * 110 + p;
        int t0 = cell ? 255 : 0;
        A0[tid * RS + 64] = __float2half(xrp[(size_t)t0 * 110]);
        A0[tid * RS + 65] = __float2half(xrp[(size_t)t0 * 110 + 55]);
        A0[tid * RS + 66] = __float2half(1.f);
        A1[tid * RS + 66] = __float2half(1.f);
    }
    __syncthreads();

    // B fragment base addresses (reloaded each step; keeps regs low for 3 blocks/SM)
    uint32_t baddr[4];
    {
        int li = lane & 15;
#pragma unroll
        for (int nt = 0; nt < 4; nt++)
            baddr[nt] = smem_u32(Bw + (wid * 32 + nt * 8 + (li & 7)) * RS
                                    + ((li >> 3) & 1) * 8);
    }

    uint32_t laneoff = (uint32_t)(((lane & 7) + 8 * ((lane >> 3) & 1)) * RS * 2
                                  + (lane >> 4) * 16);

    float cst[4] = {0.f, 0.f, 0.f, 0.f};     // rows {r0,r0+8} x chans {ch,ch+1}

    int r0 = lane >> 2;
    int ch = wid * 8 + (lane & 3) * 2;

    float xn0 = 0.f, xn1 = 0.f;

    for (int t = 0; t < 256; t++) {
        __half* Ac = (t & 1) ? A1 : A0;
        __half* An = (t & 1) ? A0 : A1;
        uint32_t abase = smem_u32(Ac) + laneoff;

        if (tid < MB && t < 255) {
            int tx = cell ? 254 - t : t + 1;
            xn0 = xrp[(size_t)tx * 110];
            xn1 = xrp[(size_t)tx * 110 + 55];
        }

        float acc[4][4];
#pragma unroll
        for (int nt = 0; nt < 4; nt++)
#pragma unroll
            for (int j = 0; j < 4; j++) acc[nt][j] = 0.f;

#pragma unroll
        for (int kt = 0; kt < 5; kt++) {
            uint32_t a0, a1, a2, a3;
            asm volatile("ldmatrix.sync.aligned.m8n8.x4.shared.b16 {%0,%1,%2,%3}, [%4];"
                         : "=r"(a0), "=r"(a1), "=r"(a2), "=r"(a3)
                         : "r"(abase + (uint32_t)(kt * 32)));
#pragma unroll
            for (int nt = 0; nt < 4; nt++) {
                uint32_t b0, b1;
                asm volatile("ldmatrix.sync.aligned.m8n8.x2.shared.b16 {%0,%1}, [%2];"
                             : "=r"(b0), "=r"(b1)
                             : "r"(baddr[nt] + (uint32_t)(kt * 32)));
                MMA16816(acc[nt], a0, a1, a2, a3, b0, b1);
            }
        }

        // epilogue: nt = gate (0:i 1:f 2:o 3:g); j: row-pair (j>>1), chan (j&1)
        float h01[2], h23[2];
#pragma unroll
        for (int j = 0; j < 4; j++) {
            float iv = sigm_pre(acc[0][j]);
            float fv = sigm_pre(acc[1][j]);
            float ov = sigm_pre(acc[2][j]);
            float gv = tanh_f(acc[3][j]);
            float cn = fmaf(fv, cst[j], iv * gv);
            cst[j] = cn;
            float h = ov * tanh_f(cn);
            if (j < 2) h01[j] = h; else h23[j - 2] = h;
        }
        *(__half2*)(An + r0 * RS + ch)       = __floats2half2_rn(h01[0], h01[1]);
        *(__half2*)(An + (r0 + 8) * RS + ch) = __floats2half2_rn(h23[0], h23[1]);

        if (t == 255) {
#pragma unroll
            for (int j = 0; j < 4; j++) {
                float h = (j < 2) ? h01[j] : h23[j - 2];
                int row = r0 + ((j >> 1) ? 8 : 0);
                int chh = ch + (j & 1);
                int ric = rb + row;
                int sub = ric / 1760, rem = ric % 1760, bb = rem / 55, pp = rem % 55;
                feat[(size_t)(sub * 32 + bb) * 7040 + cell * 3520 + chh * 55 + pp] = h;
            }
        }

        if (tid < MB && t < 255)
            *(__half2*)(An + tid * RS + 64) = __floats2half2_rn(xn0, xn1);

        __syncthreads();
    }
}

// ---------------- FC: K-split GEMM partials + reduce ----------------
__global__ __launch_bounds__(256)
void gemm_part(const float* __restrict__ X, const float* __restrict__ W,
               float* __restrict__ Ppart, int N, int K, int KS)
{
    int n0 = blockIdx.x * 64;
    int ks = blockIdx.y;
    int k0s = (int)(((long)K * ks) / KS);
    int k1s = (int)(((long)K * (ks + 1)) / KS);

    __shared__ float Asm[64][17];
    __shared__ float Bsm[16][65];

    int tid = threadIdx.x;
    int nl  = tid & 63;
    int mg  = tid >> 6;

    bool vec_ok = ((N & 3) == 0);   // float4 path only when W rows stay 16B-aligned

    float acc[16];
#pragma unroll
    for (int i = 0; i < 16; i++) acc[i] = 0.f;

    for (int k0 = k0s; k0 < k1s; k0 += 16) {
#pragma unroll
        for (int i = 0; i < 4; i++) {
            int rr = (tid >> 4) + i * 16;
            int cc = tid & 15;
            int k = k0 + cc;
            Asm[rr][cc] = (k < k1s) ? X[(size_t)rr * K + k] : 0.f;
        }
        {
            int rr = tid >> 4;            // 0..15
            int c4 = (tid & 15) * 4;      // 0..60
            int k  = k0 + rr;
            int nn = n0 + c4;
            if (vec_ok && k < k1s && nn + 3 < N) {
                float4 v = *(const float4*)&W[(size_t)k * N + nn];
                Bsm[rr][c4]     = v.x;
                Bsm[rr][c4 + 1] = v.y;
                Bsm[rr][c4 + 2] = v.z;
                Bsm[rr][c4 + 3] = v.w;
            } else {
#pragma unroll
                for (int e = 0; e < 4; e++)
                    Bsm[rr][c4 + e] = (k < k1s && nn + e < N)
                                      ? W[(size_t)k * N + nn + e] : 0.f;
            }
        }
        __syncthreads();
#pragma unroll
        for (int kk = 0; kk < 16; kk++) {
            float bv = Bsm[kk][nl];
#pragma unroll
            for (int i = 0; i < 16; i++)
                acc[i] += Asm[mg * 16 + i][kk] * bv;
        }
        __syncthreads();
    }

    int nn = n0 + nl;
    if (nn < N) {
        float* outp = Ppart + (size_t)ks * 64 * N;
#pragma unroll
        for (int i = 0; i < 16; i++)
            outp[(size_t)(mg * 16 + i) * N + nn] = acc[i];
    }
}

__global__ void reduce_bias(const float* __restrict__ Ppart, const float* __restrict__ bias,
                            float* __restrict__ Y, int N, int KS)
{
    int idx = blockIdx.x * 256 + threadIdx.x;
    if (idx >= 64 * N) return;
    int nn = idx % N;
    float s = bias[nn];
    for (int ks = 0; ks < KS; ks++) s += Ppart[(size_t)ks * 64 * N + idx];
    Y[idx] = s;
}

// ---------------- launch ----------------
extern "C" void kernel_launch(void* const* d_in, const int* in_sizes, int n_in,
                              void* d_out, int out_size)
{
    const float* x1  = (const float*)d_in[0];
    const float* x2  = (const float*)d_in[1];
    const float* wx1 = (const float*)d_in[2];
    const float* wh1 = (const float*)d_in[3];
    const float* bx1 = (const float*)d_in[4];
    const float* bh1 = (const float*)d_in[5];
    const float* wx2 = (const float*)d_in[6];
    const float* wh2 = (const float*)d_in[7];
    const float* bx2 = (const float*)d_in[8];
    const float* bh2 = (const float*)d_in[9];
    const float* fw2 = (const float*)d_in[10];
    const float* fb2 = (const float*)d_in[11];
    const float* fw3 = (const float*)d_in[12];
    const float* fb3 = (const float*)d_in[13];
    const float* fw4 = (const float*)d_in[14];
    const float* fb4 = (const float*)d_in[15];
    const float* fw5 = (const float*)d_in[16];
    const float* fb5 = (const float*)d_in[17];

    float *feat, *y1, *y2, *y3, *part;
    cudaGetSymbolAddress((void**)&feat, g_feat);
    cudaGetSymbolAddress((void**)&y1,   g_y1);
    cudaGetSymbolAddress((void**)&y2,   g_y2);
    cudaGetSymbolAddress((void**)&y3,   g_y3);
    cudaGetSymbolAddress((void**)&part, g_part);

    cudaFuncSetAttribute(lstm_mma, cudaFuncAttributeMaxDynamicSharedMemorySize, SMEM_BYTES);

    lstm_mma<<<440, 256, SMEM_BYTES>>>(x1, x2, wx1, wh1, bx1, bh1,
                                       wx2, wh2, bx2, bh2, feat);

    // FC1: 7040 -> 3400
    gemm_part<<<dim3(54, 16), 256>>>(feat, fw2, part, 3400, 7040, 16);
    reduce_bias<<<(64 * 3400 + 255) / 256, 256>>>(part, fb2, y1, 3400, 16);
    // FC2: 3400 -> 1000
    gemm_part<<<dim3(16, 8), 256>>>(y1, fw3, part, 1000, 3400, 8);
    reduce_bias<<<(64 * 1000 + 255) / 256, 256>>>(part, fb3, y2, 1000, 8);
    // FC3: 1000 -> 500
    gemm_part<<<dim3(8, 4), 256>>>(y2, fw4, part, 500, 1000, 4);
    reduce_bias<<<(64 * 500 + 255) / 256, 256>>>(part, fb4, y3, 500, 4);
    // FC4: 500 -> 50 -> d_out
    gemm_part<<<dim3(1, 2), 256>>>(y3, fw5, part, 50, 500, 2);
    reduce_bias<<<(64 * 50 + 255) / 256, 256>>>(part, fb5, (float*)d_out, 50, 2);
}

// round 12
// speedup vs baseline: 1.0005x; 1.0005x over previous
#include <cuda_runtime.h>
#include <cuda_fp16.h>
#include <cstdint>

#define RS   88                 // halves per smem row (176 B)
#define MB   16                 // rows per block
#define ASZH (MB * RS)          // halves per A buffer
#define SMEM_BYTES ((2 * ASZH + 256 * RS) * 2)   // 50688

// ---------------- scratch ----------------
__device__ float g_feat[2 * 32 * 2 * 64 * 55];   // [sub][b][7040]
__device__ float g_y1[64 * 3400];
__device__ float g_y2[64 * 1000];
__device__ float g_y3[64 * 512];
__device__ float g_part[16 * 64 * 3400];

__device__ __forceinline__ float tanh_f(float x) {
    float r; asm("tanh.approx.f32 %0, %1;" : "=f"(r) : "f"(x)); return r;
}
// pre-activation already scaled by 0.5 (folded into weights)
__device__ __forceinline__ float sigm_pre(float xhalf) {
    return fmaf(0.5f, tanh_f(xhalf), 0.5f);
}

__device__ __forceinline__ uint32_t smem_u32(const void* p) {
    uint32_t a;
    asm("{ .reg .u64 t; cvta.to.shared.u64 t, %1; cvt.u32.u64 %0, t; }" : "=r"(a) : "l"(p));
    return a;
}

#define MMA16816(d, a0, a1, a2, a3, b0, b1) \
    asm volatile("mma.sync.aligned.m16n8k16.row.col.f32.f16.f16.f32 " \
        "{%0,%1,%2,%3}, {%4,%5,%6,%7}, {%8,%9}, {%0,%1,%2,%3};" \
        : "+f"((d)[0]), "+f"((d)[1]), "+f"((d)[2]), "+f"((d)[3]) \
        : "r"(a0), "r"(a1), "r"(a2), "r"(a3), "r"(b0), "r"(b1))

// ---------------- tensor-core LSTM (HMMA, 3 blocks/SM) ----------------
// grid = 440: blk/220 = cell, rb = (blk%220)*16 (exact, no padding).
// Warp w owns B cols [32w,32w+32): col n -> gate (n>>3)&3, channel 8w + (n&7).
// Lane owns rows {lane>>2, +8}, channels {8w+(lane&3)*2, +1}; full gate quad in-lane.
__global__ __launch_bounds__(256, 3)
void lstm_mma(const float* __restrict__ x1, const float* __restrict__ x2,
              const float* __restrict__ wx1, const float* __restrict__ wh1,
              const float* __restrict__ bx1, const float* __restrict__ bh1,
              const float* __restrict__ wx2, const float* __restrict__ wh2,
              const float* __restrict__ bx2, const float* __restrict__ bh2,
              float* __restrict__ feat)
{
    extern __shared__ __align__(16) __half smem[];
    __half* A0 = smem;
    __half* A1 = smem + ASZH;
    __half* Bw = smem + 2 * ASZH;

    int tid = threadIdx.x, wid = tid >> 5, lane = tid & 31;
    int blk = blockIdx.x;
    int cell = blk / 220;
    int rb   = (blk % 220) * MB;             // row base within cell-space (always full)

    const float* wh = cell ? wh2 : wh1;
    const float* wx = cell ? wx2 : wx1;
    const float* bx = cell ? bx2 : bx1;
    const float* bh = cell ? bh2 : bh1;

    // ---- build B (fp16, 0.5-prescaled for sigmoid gates i,f,o) ----
    {
        int n  = tid;
        int w  = n >> 5, g = (n >> 3) & 3, cl = n & 7;
        int gc = g * 64 + 8 * w + cl;        // source gate column
        float s = (g == 3) ? 1.0f : 0.5f;
        __half* bp = Bw + n * RS;
#pragma unroll 8
        for (int k = 0; k < 64; k++) bp[k] = __float2half(wh[k * 256 + gc] * s);
        bp[64] = __float2half(wx[gc] * s);
        bp[65] = __float2half(wx[256 + gc] * s);
        bp[66] = __float2half((bx[gc] + bh[gc]) * s);
#pragma unroll
        for (int k = 67; k < RS; k++) bp[k] = __float2half(0.f);
    }
    // ---- zero A buffers ----
    for (int i = tid; i < (2 * ASZH * 2) / 16; i += 256)
        ((uint4*)smem)[i] = make_uint4(0, 0, 0, 0);
    __syncthreads();

    // per-row x pointer (threads 0..15 own row tid)
    const float* xrp = nullptr;
    if (tid < MB) {
        int ric = rb + tid;
        int sub = ric / 1760, rem = ric % 1760, b = rem / 55, p = rem % 55;
        xrp = (sub ? x2 : x1) + (size_t)b * 256 * 110 + p;
        int t0 = cell ? 255 : 0;
        A0[tid * RS + 64] = __float2half(xrp[(size_t)t0 * 110]);
        A0[tid * RS + 65] = __float2half(xrp[(size_t)t0 * 110 + 55]);
        A0[tid * RS + 66] = __float2half(1.f);
        A1[tid * RS + 66] = __float2half(1.f);
    }
    __syncthreads();

    // B fragment base addresses (reloaded each step; keeps regs low for 3 blocks/SM)
    uint32_t baddr[4];
    {
        int li = lane & 15;
#pragma unroll
        for (int nt = 0; nt < 4; nt++)
            baddr[nt] = smem_u32(Bw + (wid * 32 + nt * 8 + (li & 7)) * RS
                                    + ((li >> 3) & 1) * 8);
    }

    uint32_t laneoff = (uint32_t)(((lane & 7) + 8 * ((lane >> 3) & 1)) * RS * 2
                                  + (lane >> 4) * 16);

    float cst[4] = {0.f, 0.f, 0.f, 0.f};     // rows {r0,r0+8} x chans {ch,ch+1}

    int r0 = lane >> 2;
    int ch = wid * 8 + (lane & 3) * 2;

    float xn0 = 0.f, xn1 = 0.f;

    for (int t = 0; t < 256; t++) {
        __half* Ac = (t & 1) ? A1 : A0;
        __half* An = (t & 1) ? A0 : A1;
        uint32_t abase = smem_u32(Ac) + laneoff;

        if (tid < MB && t < 255) {
            int tx = cell ? 254 - t : t + 1;
            xn0 = xrp[(size_t)tx * 110];
            xn1 = xrp[(size_t)tx * 110 + 55];
        }

        float acc[4][4];
#pragma unroll
        for (int nt = 0; nt < 4; nt++)
#pragma unroll
            for (int j = 0; j < 4; j++) acc[nt][j] = 0.f;

#pragma unroll
        for (int kt = 0; kt < 5; kt++) {
            uint32_t a0, a1, a2, a3;
            asm volatile("ldmatrix.sync.aligned.m8n8.x4.shared.b16 {%0,%1,%2,%3}, [%4];"
                         : "=r"(a0), "=r"(a1), "=r"(a2), "=r"(a3)
                         : "r"(abase + (uint32_t)(kt * 32)));
#pragma unroll
            for (int nt = 0; nt < 4; nt++) {
                uint32_t b0, b1;
                asm volatile("ldmatrix.sync.aligned.m8n8.x2.shared.b16 {%0,%1}, [%2];"
                             : "=r"(b0), "=r"(b1)
                             : "r"(baddr[nt] + (uint32_t)(kt * 32)));
                MMA16816(acc[nt], a0, a1, a2, a3, b0, b1);
            }
        }

        // epilogue: nt = gate (0:i 1:f 2:o 3:g); j: row-pair (j>>1), chan (j&1)
        float h01[2], h23[2];
#pragma unroll
        for (int j = 0; j < 4; j++) {
            float iv = sigm_pre(acc[0][j]);
            float fv = sigm_pre(acc[1][j]);
            float ov = sigm_pre(acc[2][j]);
            float gv = tanh_f(acc[3][j]);
            float cn = fmaf(fv, cst[j], iv * gv);
            cst[j] = cn;
            float h = ov * tanh_f(cn);
            if (j < 2) h01[j] = h; else h23[j - 2] = h;
        }
        *(__half2*)(An + r0 * RS + ch)       = __floats2half2_rn(h01[0], h01[1]);
        *(__half2*)(An + (r0 + 8) * RS + ch) = __floats2half2_rn(h23[0], h23[1]);

        if (t == 255) {
#pragma unroll
            for (int j = 0; j < 4; j++) {
                float h = (j < 2) ? h01[j] : h23[j - 2];
                int row = r0 + ((j >> 1) ? 8 : 0);
                int chh = ch + (j & 1);
                int ric = rb + row;
                int sub = ric / 1760, rem = ric % 1760, bb = rem / 55, pp = rem % 55;
                feat[(size_t)(sub * 32 + bb) * 7040 + cell * 3520 + chh * 55 + pp] = h;
            }
        }

        if (tid < MB && t < 255)
            *(__half2*)(An + tid * RS + 64) = __floats2half2_rn(xn0, xn1);

        __syncthreads();
    }
}

// ---------------- FC: K-split GEMM partials + reduce ----------------
__global__ __launch_bounds__(256)
void gemm_part(const float* __restrict__ X, const float* __restrict__ W,
               float* __restrict__ Ppart, int N, int K, int KS)
{
    int n0 = blockIdx.x * 64;
    int ks = blockIdx.y;
    int k0s = (int)(((long)K * ks) / KS);
    int k1s = (int)(((long)K * (ks + 1)) / KS);

    __shared__ float Asm[64][17];
    __shared__ float Bsm[16][65];

    int tid = threadIdx.x;
    int nl  = tid & 63;
    int mg  = tid >> 6;

    bool vec_ok = ((N & 3) == 0);   // float4 path only when W rows stay 16B-aligned

    float acc[16];
#pragma unroll
    for (int i = 0; i < 16; i++) acc[i] = 0.f;

    for (int k0 = k0s; k0 < k1s; k0 += 16) {
#pragma unroll
        for (int i = 0; i < 4; i++) {
            int rr = (tid >> 4) + i * 16;
            int cc = tid & 15;
            int k = k0 + cc;
            Asm[rr][cc] = (k < k1s) ? X[(size_t)rr * K + k] : 0.f;
        }
        {
            int rr = tid >> 4;            // 0..15
            int c4 = (tid & 15) * 4;      // 0..60
            int k  = k0 + rr;
            int nn = n0 + c4;
            if (vec_ok && k < k1s && nn + 3 < N) {
                float4 v = *(const float4*)&W[(size_t)k * N + nn];
                Bsm[rr][c4]     = v.x;
                Bsm[rr][c4 + 1] = v.y;
                Bsm[rr][c4 + 2] = v.z;
                Bsm[rr][c4 + 3] = v.w;
            } else {
#pragma unroll
                for (int e = 0; e < 4; e++)
                    Bsm[rr][c4 + e] = (k < k1s && nn + e < N)
                                      ? W[(size_t)k * N + nn + e] : 0.f;
            }
        }
        __syncthreads();
#pragma unroll
        for (int kk = 0; kk < 16; kk++) {
            float bv = Bsm[kk][nl];
#pragma unroll
            for (int i = 0; i < 16; i++)
                acc[i] += Asm[mg * 16 + i][kk] * bv;
        }
        __syncthreads();
    }

    int nn = n0 + nl;
    if (nn < N) {
        float* outp = Ppart + (size_t)ks * 64 * N;
#pragma unroll
        for (int i = 0; i < 16; i++)
            outp[(size_t)(mg * 16 + i) * N + nn] = acc[i];
    }
}

__global__ void reduce_bias(const float* __restrict__ Ppart, const float* __restrict__ bias,
                            float* __restrict__ Y, int N, int KS)
{
    int idx = blockIdx.x * 256 + threadIdx.x;
    if (idx >= 64 * N) return;
    int nn = idx % N;
    float s = bias[nn];
    for (int ks = 0; ks < KS; ks++) s += Ppart[(size_t)ks * 64 * N + idx];
    Y[idx] = s;
}

// ---------------- launch ----------------
extern "C" void kernel_launch(void* const* d_in, const int* in_sizes, int n_in,
                              void* d_out, int out_size)
{
    const float* x1  = (const float*)d_in[0];
    const float* x2  = (const float*)d_in[1];
    const float* wx1 = (const float*)d_in[2];
    const float* wh1 = (const float*)d_in[3];
    const float* bx1 = (const float*)d_in[4];
    const float* bh1 = (const float*)d_in[5];
    const float* wx2 = (const float*)d_in[6];
    const float* wh2 = (const float*)d_in[7];
    const float* bx2 = (const float*)d_in[8];
    const float* bh2 = (const float*)d_in[9];
    const float* fw2 = (const float*)d_in[10];
    const float* fb2 = (const float*)d_in[11];
    const float* fw3 = (const float*)d_in[12];
    const float* fb3 = (const float*)d_in[13];
    const float* fw4 = (const float*)d_in[14];
    const float* fb4 = (const float*)d_in[15];
    const float* fw5 = (const float*)d_in[16];
    const float* fb5 = (const float*)d_in[17];

    float *feat, *y1, *y2, *y3, *part;
    cudaGetSymbolAddress((void**)&feat, g_feat);
    cudaGetSymbolAddress((void**)&y1,   g_y1);
    cudaGetSymbolAddress((void**)&y2,   g_y2);
    cudaGetSymbolAddress((void**)&y3,   g_y3);
    cudaGetSymbolAddress((void**)&part, g_part);

    cudaFuncSetAttribute(lstm_mma, cudaFuncAttributeMaxDynamicSharedMemorySize, SMEM_BYTES);

    lstm_mma<<<440, 256, SMEM_BYTES>>>(x1, x2, wx1, wh1, bx1, bh1,
                                       wx2, wh2, bx2, bh2, feat);

    // FC1: 7040 -> 3400
    gemm_part<<<dim3(54, 16), 256>>>(feat, fw2, part, 3400, 7040, 16);
    reduce_bias<<<(64 * 3400 + 255) / 256, 256>>>(part, fb2, y1, 3400, 16);
    // FC2: 3400 -> 1000
    gemm_part<<<dim3(16, 8), 256>>>(y1, fw3, part, 1000, 3400, 8);
    reduce_bias<<<(64 * 1000 + 255) / 256, 256>>>(part, fb3, y2, 1000, 8);
    // FC3: 1000 -> 500
    gemm_part<<<dim3(8, 4), 256>>>(y2, fw4, part, 500, 1000, 4);
    reduce_bias<<<(64 * 500 + 255) / 256, 256>>>(part, fb4, y3, 500, 4);
    // FC4: 500 -> 50 -> d_out
    gemm_part<<<dim3(1, 2), 256>>>(y3, fw5, part, 50, 500, 2);
    reduce_bias<<<(64 * 50 + 255) / 256, 256>>>(part, fb5, (float*)d_out, 50, 2);
}

// round 13
// speedup vs baseline: 1.0489x; 1.0484x over previous
#include <cuda_runtime.h>
#include <cuda_fp16.h>
#include <cstdint>

#define RS   88                 // halves per smem row (176 B)
#define MB   16                 // rows per block
#define ASZH (MB * RS)          // halves per A buffer
#define SMEM_BYTES ((2 * ASZH + 256 * RS) * 2)   // 50688

// ---------------- scratch ----------------
__device__ float g_feat[2 * 32 * 2 * 64 * 55];   // [sub][b][7040]
__device__ float g_y1[64 * 3400];
__device__ float g_y2[64 * 1000];
__device__ float g_y3[64 * 512];
__device__ float g_part[16 * 64 * 3400];

__device__ __forceinline__ __half2 tanh_h2(__half2 x) {
    uint32_t v = *(uint32_t*)&x, r;
    asm("tanh.approx.f16x2 %0, %1;" : "=r"(r) : "r"(v));
    return *(__half2*)&r;
}

__device__ __forceinline__ uint32_t smem_u32(const void* p) {
    uint32_t a;
    asm("{ .reg .u64 t; cvta.to.shared.u64 t, %1; cvt.u32.u64 %0, t; }" : "=r"(a) : "l"(p));
    return a;
}

#define MMA16816(d, a0, a1, a2, a3, b0, b1) \
    asm volatile("mma.sync.aligned.m16n8k16.row.col.f32.f16.f16.f32 " \
        "{%0,%1,%2,%3}, {%4,%5,%6,%7}, {%8,%9}, {%0,%1,%2,%3};" \
        : "+f"((d)[0]), "+f"((d)[1]), "+f"((d)[2]), "+f"((d)[3]) \
        : "r"(a0), "r"(a1), "r"(a2), "r"(a3), "r"(b0), "r"(b1))

// ---------------- tensor-core LSTM (HMMA, 3 blocks/SM, f16x2 epilogue) ----------------
// grid = 440: blk/220 = cell, rb = (blk%220)*16 (exact).
// Warp w owns B cols [32w,32w+32): col n -> gate (n>>3)&3, channel 8w + (n&7).
// Lane owns rows {lane>>2, +8}, channels {8w+(lane&3)*2, +1}; full gate quad in-lane.
__global__ __launch_bounds__(256, 3)
void lstm_mma(const float* __restrict__ x1, const float* __restrict__ x2,
              const float* __restrict__ wx1, const float* __restrict__ wh1,
              const float* __restrict__ bx1, const float* __restrict__ bh1,
              const float* __restrict__ wx2, const float* __restrict__ wh2,
              const float* __restrict__ bx2, const float* __restrict__ bh2,
              float* __restrict__ feat)
{
    extern __shared__ __align__(16) __half smem[];
    __half* A0 = smem;
    __half* A1 = smem + ASZH;
    __half* Bw = smem + 2 * ASZH;

    int tid = threadIdx.x, wid = tid >> 5, lane = tid & 31;
    int blk = blockIdx.x;
    int cell = blk / 220;
    int rb   = (blk % 220) * MB;

    const float* wh = cell ? wh2 : wh1;
    const float* wx = cell ? wx2 : wx1;
    const float* bx = cell ? bx2 : bx1;
    const float* bh = cell ? bh2 : bh1;

    // ---- build B (fp16, 0.5-prescaled for sigmoid gates i,f,o) ----
    {
        int n  = tid;
        int w  = n >> 5, g = (n >> 3) & 3, cl = n & 7;
        int gc = g * 64 + 8 * w + cl;        // source gate column
        float s = (g == 3) ? 1.0f : 0.5f;
        __half* bp = Bw + n * RS;
#pragma unroll 8
        for (int k = 0; k < 64; k++) bp[k] = __float2half(wh[k * 256 + gc] * s);
        bp[64] = __float2half(wx[gc] * s);
        bp[65] = __float2half(wx[256 + gc] * s);
        bp[66] = __float2half((bx[gc] + bh[gc]) * s);
#pragma unroll
        for (int k = 67; k < RS; k++) bp[k] = __float2half(0.f);
    }
    // ---- zero A buffers ----
    for (int i = tid; i < (2 * ASZH * 2) / 16; i += 256)
        ((uint4*)smem)[i] = make_uint4(0, 0, 0, 0);
    __syncthreads();

    // per-row x pointer (threads 0..15 own row tid)
    const float* xrp = nullptr;
    if (tid < MB) {
        int ric = rb + tid;
        int sub = ric / 1760, rem = ric % 1760, b = rem / 55, p = rem % 55;
        xrp = (sub ? x2 : x1) + (size_t)b * 256 * 110 + p;
        int t0 = cell ? 255 : 0;
        A0[tid * RS + 64] = __float2half(xrp[(size_t)t0 * 110]);
        A0[tid * RS + 65] = __float2half(xrp[(size_t)t0 * 110 + 55]);
        A0[tid * RS + 66] = __float2half(1.f);
        A1[tid * RS + 66] = __float2half(1.f);
    }
    __syncthreads();

    // B x4-ldmatrix bases: pair P covers nt=2P,2P+1 (16 B-rows).
    // lane group g=lane>>3: m0=rows+0,k0  m1=rows+0,k8  m2=rows+8,k0  m3=rows+8,k8
    uint32_t baddr2[2];
#pragma unroll
    for (int P = 0; P < 2; P++)
        baddr2[P] = smem_u32(Bw + (wid * 32 + P * 16 + ((lane >> 4) * 8) + (lane & 7)) * RS
                                + (((lane >> 3) & 1) * 8));

    uint32_t laneoff = (uint32_t)(((lane & 7) + 8 * ((lane >> 3) & 1)) * RS * 2
                                  + (lane >> 4) * 16);

    const __half2 h05 = __floats2half2_rn(0.5f, 0.5f);
    __half2 cst2[2];
    cst2[0] = __floats2half2_rn(0.f, 0.f);
    cst2[1] = __floats2half2_rn(0.f, 0.f);

    int r0 = lane >> 2;
    int ch = wid * 8 + (lane & 3) * 2;

    float xn0 = 0.f, xn1 = 0.f;

    for (int t = 0; t < 256; t++) {
        __half* Ac = (t & 1) ? A1 : A0;
        __half* An = (t & 1) ? A0 : A1;
        uint32_t abase = smem_u32(Ac) + laneoff;

        if (tid < MB && t < 255) {
            int tx = cell ? 254 - t : t + 1;
            xn0 = xrp[(size_t)tx * 110];
            xn1 = xrp[(size_t)tx * 110 + 55];
        }

        float acc[4][4];
#pragma unroll
        for (int nt = 0; nt < 4; nt++)
#pragma unroll
            for (int j = 0; j < 4; j++) acc[nt][j] = 0.f;

#pragma unroll
        for (int kt = 0; kt < 5; kt++) {
            uint32_t a0, a1, a2, a3;
            asm volatile("ldmatrix.sync.aligned.m8n8.x4.shared.b16 {%0,%1,%2,%3}, [%4];"
                         : "=r"(a0), "=r"(a1), "=r"(a2), "=r"(a3)
                         : "r"(abase + (uint32_t)(kt * 32)));
            uint32_t b0, b1, b2, b3;
            asm volatile("ldmatrix.sync.aligned.m8n8.x4.shared.b16 {%0,%1,%2,%3}, [%4];"
                         : "=r"(b0), "=r"(b1), "=r"(b2), "=r"(b3)
                         : "r"(baddr2[0] + (uint32_t)(kt * 32)));
            MMA16816(acc[0], a0, a1, a2, a3, b0, b1);
            MMA16816(acc[1], a0, a1, a2, a3, b2, b3);
            asm volatile("ldmatrix.sync.aligned.m8n8.x4.shared.b16 {%0,%1,%2,%3}, [%4];"
                         : "=r"(b0), "=r"(b1), "=r"(b2), "=r"(b3)
                         : "r"(baddr2[1] + (uint32_t)(kt * 32)));
            MMA16816(acc[2], a0, a1, a2, a3, b0, b1);
            MMA16816(acc[3], a0, a1, a2, a3, b2, b3);
        }

        // f16x2 epilogue: pair p = row (r0 + 8p), chans (ch, ch+1)
#pragma unroll
        for (int p = 0; p < 2; p++) {
            __half2 iv = tanh_h2(__floats2half2_rn(acc[0][2*p], acc[0][2*p+1]));
            __half2 fv = tanh_h2(__floats2half2_rn(acc[1][2*p], acc[1][2*p+1]));
            __half2 ov = tanh_h2(__floats2half2_rn(acc[2][2*p], acc[2][2*p+1]));
            __half2 gv = tanh_h2(__floats2half2_rn(acc[3][2*p], acc[3][2*p+1]));
            iv = __hfma2(iv, h05, h05);
            fv = __hfma2(fv, h05, h05);
            ov = __hfma2(ov, h05, h05);
            __half2 cn = __hfma2(fv, cst2[p], __hmul2(iv, gv));
            cst2[p] = cn;
            __half2 h2 = __hmul2(ov, tanh_h2(cn));
            *(__half2*)(An + (r0 + p * 8) * RS + ch) = h2;

            if (t == 255) {
                float2 hf = __half22float2(h2);
                int row = r0 + p * 8;
                int ric = rb + row;
                int sub = ric / 1760, rem = ric % 1760, bb = rem / 55, pp = rem % 55;
                size_t base = (size_t)(sub * 32 + bb) * 7040 + cell * 3520 + pp;
                feat[base + (size_t)ch * 55]       = hf.x;
                feat[base + (size_t)(ch + 1) * 55] = hf.y;
            }
        }

        if (tid < MB && t < 255)
            *(__half2*)(An + tid * RS + 64) = __floats2half2_rn(xn0, xn1);

        __syncthreads();
    }
}

// ---------------- FC: K-split GEMM partials + reduce ----------------
__global__ __launch_bounds__(256)
void gemm_part(const float* __restrict__ X, const float* __restrict__ W,
               float* __restrict__ Ppart, int N, int K, int KS)
{
    int n0 = blockIdx.x * 64;
    int ks = blockIdx.y;
    int k0s = (int)(((long)K * ks) / KS);
    int k1s = (int)(((long)K * (ks + 1)) / KS);

    __shared__ float Asm[64][17];
    __shared__ float Bsm[16][65];

    int tid = threadIdx.x;
    int nl  = tid & 63;
    int mg  = tid >> 6;

    bool vec_ok = ((N & 3) == 0);

    float acc[16];
#pragma unroll
    for (int i = 0; i < 16; i++) acc[i] = 0.f;

    for (int k0 = k0s; k0 < k1s; k0 += 16) {
#pragma unroll
        for (int i = 0; i < 4; i++) {
            int rr = (tid >> 4) + i * 16;
            int cc = tid & 15;
            int k = k0 + cc;
            Asm[rr][cc] = (k < k1s) ? X[(size_t)rr * K + k] : 0.f;
        }
        {
            int rr = tid >> 4;
            int c4 = (tid & 15) * 4;
            int k  = k0 + rr;
            int nn = n0 + c4;
            if (vec_ok && k < k1s && nn + 3 < N) {
                float4 v = *(const float4*)&W[(size_t)k * N + nn];
                Bsm[rr][c4]     = v.x;
                Bsm[rr][c4 + 1] = v.y;
                Bsm[rr][c4 + 2] = v.z;
                Bsm[rr][c4 + 3] = v.w;
            } else {
#pragma unroll
                for (int e = 0; e < 4; e++)
                    Bsm[rr][c4 + e] = (k < k1s && nn + e < N)
                                      ? W[(size_t)k * N + nn + e] : 0.f;
            }
        }
        __syncthreads();
#pragma unroll
        for (int kk = 0; kk < 16; kk++) {
            float bv = Bsm[kk][nl];
#pragma unroll
            for (int i = 0; i < 16; i++)
                acc[i] += Asm[mg * 16 + i][kk] * bv;
        }
        __syncthreads();
    }

    int nn = n0 + nl;
    if (nn < N) {
        float* outp = Ppart + (size_t)ks * 64 * N;
#pragma unroll
        for (int i = 0; i < 16; i++)
            outp[(size_t)(mg * 16 + i) * N + nn] = acc[i];
    }
}

__global__ void reduce_bias(const float* __restrict__ Ppart, const float* __restrict__ bias,
                            float* __restrict__ Y, int N, int KS)
{
    int idx = blockIdx.x * 256 + threadIdx.x;
    if (idx >= 64 * N) return;
    int nn = idx % N;
    float s = bias[nn];
    for (int ks = 0; ks < KS; ks++) s += Ppart[(size_t)ks * 64 * N + idx];
    Y[idx] = s;
}

// ---------------- launch ----------------
extern "C" void kernel_launch(void* const* d_in, const int* in_sizes, int n_in,
                              void* d_out, int out_size)
{
    const float* x1  = (const float*)d_in[0];
    const float* x2  = (const float*)d_in[1];
    const float* wx1 = (const float*)d_in[2];
    const float* wh1 = (const float*)d_in[3];
    const float* bx1 = (const float*)d_in[4];
    const float* bh1 = (const float*)d_in[5];
    const float* wx2 = (const float*)d_in[6];
    const float* wh2 = (const float*)d_in[7];
    const float* bx2 = (const float*)d_in[8];
    const float* bh2 = (const float*)d_in[9];
    const float* fw2 = (const float*)d_in[10];
    const float* fb2 = (const float*)d_in[11];
    const float* fw3 = (const float*)d_in[12];
    const float* fb3 = (const float*)d_in[13];
    const float* fw4 = (const float*)d_in[14];
    const float* fb4 = (const float*)d_in[15];
    const float* fw5 = (const float*)d_in[16];
    const float* fb5 = (const float*)d_in[17];

    float *feat, *y1, *y2, *y3, *part;
    cudaGetSymbolAddress((void**)&feat, g_feat);
    cudaGetSymbolAddress((void**)&y1,   g_y1);
    cudaGetSymbolAddress((void**)&y2,   g_y2);
    cudaGetSymbolAddress((void**)&y3,   g_y3);
    cudaGetSymbolAddress((void**)&part, g_part);

    cudaFuncSetAttribute(lstm_mma, cudaFuncAttributeMaxDynamicSharedMemorySize, SMEM_BYTES);

    lstm_mma<<<440, 256, SMEM_BYTES>>>(x1, x2, wx1, wh1, bx1, bh1,
                                       wx2, wh2, bx2, bh2, feat);

    // FC1: 7040 -> 3400
    gemm_part<<<dim3(54, 16), 256>>>(feat, fw2, part, 3400, 7040, 16);
    reduce_bias<<<(64 * 3400 + 255) / 256, 256>>>(part, fb2, y1, 3400, 16);
    // FC2: 3400 -> 1000
    gemm_part<<<dim3(16, 8), 256>>>(y1, fw3, part, 1000, 3400, 8);
    reduce_bias<<<(64 * 1000 + 255) / 256, 256>>>(part, fb3, y2, 1000, 8);
    // FC3: 1000 -> 500
    gemm_part<<<dim3(8, 4), 256>>>(y2, fw4, part, 500, 1000, 4);
    reduce_bias<<<(64 * 500 + 255) / 256, 256>>>(part, fb4, y3, 500, 4);
    // FC4: 500 -> 50 -> d_out
    gemm_part<<<dim3(1, 2), 256>>>(y3, fw5, part, 50, 500, 2);
    reduce_bias<<<(64 * 50 + 255) / 256, 256>>>(part, fb5, (float*)d_out, 50, 2);
}

// round 14
// speedup vs baseline: 1.0946x; 1.0436x over previous
#include <cuda_runtime.h>
#include <cuda_fp16.h>
#include <cstdint>

#define RS   88                 // halves per smem row (176 B, conflict-free)
#define MB   16                 // rows per block
#define ASZH (MB * RS)          // halves per A buffer
#define XSOFF (2 * ASZH + 256 * RS)              // half2 x-ring after B
#define SMEM_BYTES ((XSOFF + 64) * 2)            // + 2 bufs x 16 half2

// ---------------- scratch ----------------
__device__ float g_feat[2 * 32 * 2 * 64 * 55];   // [sub][b][7040]
__device__ float g_y1[64 * 3400];
__device__ float g_y2[64 * 1000];
__device__ float g_y3[64 * 512];
__device__ float g_part[16 * 64 * 3400];

__device__ __forceinline__ __half2 tanh_h2(__half2 x) {
    uint32_t v = *(uint32_t*)&x, r;
    asm("tanh.approx.f16x2 %0, %1;" : "=r"(r) : "r"(v));
    return *(__half2*)&r;
}
__device__ __forceinline__ __half2 u2h(uint32_t v) { return *(__half2*)&v; }

__device__ __forceinline__ uint32_t smem_u32(const void* p) {
    uint32_t a;
    asm("{ .reg .u64 t; cvta.to.shared.u64 t, %1; cvt.u32.u64 %0, t; }" : "=r"(a) : "l"(p));
    return a;
}

// fp16-accumulator HMMA
#define MMA16816H(d0, d1, a0, a1, a2, a3, b0, b1) \
    asm volatile("mma.sync.aligned.m16n8k16.row.col.f16.f16.f16.f16 " \
        "{%0,%1}, {%2,%3,%4,%5}, {%6,%7}, {%0,%1};" \
        : "+r"(d0), "+r"(d1) \
        : "r"(a0), "r"(a1), "r"(a2), "r"(a3), "r"(b0), "r"(b1))

// ---------------- tensor-core LSTM (HMMA f16-accum, K=64, 3 blocks/SM) ----------------
// grid = 440: blk/220 = cell, rb = (blk%220)*16.
// Warp w owns B cols [32w,32w+32): col n -> gate (n>>3)&3, channel 8w + (n&7).
// Lane owns rows {lane>>2, +8}, channels {8w+(lane&3)*2, +1}; full gate quad in-lane.
// d0 half2 = (row r0, ch/ch+1), d1 = (row r0+8, ch/ch+1).
__global__ __launch_bounds__(256, 3)
void lstm_mma(const float* __restrict__ x1, const float* __restrict__ x2,
              const float* __restrict__ wx1, const float* __restrict__ wh1,
              const float* __restrict__ bx1, const float* __restrict__ bh1,
              const float* __restrict__ wx2, const float* __restrict__ wh2,
              const float* __restrict__ bx2, const float* __restrict__ bh2,
              float* __restrict__ feat)
{
    extern __shared__ __align__(16) __half smem[];
    __half*  A0 = smem;
    __half*  A1 = smem + ASZH;
    __half*  Bw = smem + 2 * ASZH;
    __half2* xs = (__half2*)(smem + XSOFF);      // [2][16]

    int tid = threadIdx.x, wid = tid >> 5, lane = tid & 31;
    int blk = blockIdx.x;
    int cell = blk / 220;
    int rb   = (blk % 220) * MB;

    const float* wh = cell ? wh2 : wh1;
    const float* wx = cell ? wx2 : wx1;
    const float* bx = cell ? bx2 : bx1;
    const float* bh = cell ? bh2 : bh1;

    // ---- build B (fp16, 0.5-prescaled for sigmoid gates i,f,o), K=64 only ----
    {
        int n  = tid;
        int w  = n >> 5, g = (n >> 3) & 3, cl = n & 7;
        int gc = g * 64 + 8 * w + cl;
        float s = (g == 3) ? 1.0f : 0.5f;
        __half* bp = Bw + n * RS;
#pragma unroll 8
        for (int k = 0; k < 64; k++) bp[k] = __float2half(wh[k * 256 + gc] * s);
#pragma unroll
        for (int k = 64; k < RS; k++) bp[k] = __float2half(0.f);
    }
    // ---- zero A buffers ----
    for (int i = tid; i < (2 * ASZH * 2) / 16; i += 256)
        ((uint4*)smem)[i] = make_uint4(0, 0, 0, 0);
    __syncthreads();

    // ---- per-thread gx constants: gates nt, channels ch, ch+1 ----
    int r0 = lane >> 2;
    int ch = wid * 8 + (lane & 3) * 2;
    __half2 wxa2[4], wxb2[4], bb2[4];
#pragma unroll
    for (int nt = 0; nt < 4; nt++) {
        float s = (nt == 3) ? 1.0f : 0.5f;
        int g0 = nt * 64 + ch, g1 = g0 + 1;
        wxa2[nt] = __floats2half2_rn(wx[g0] * s,       wx[g1] * s);
        wxb2[nt] = __floats2half2_rn(wx[256 + g0] * s, wx[256 + g1] * s);
        bb2[nt]  = __floats2half2_rn((bx[g0] + bh[g0]) * s, (bx[g1] + bh[g1]) * s);
    }

    // per-row x pointer (threads 0..15 own row tid)
    const float* xrp = nullptr;
    if (tid < MB) {
        int ric = rb + tid;
        int sub = ric / 1760, rem = ric % 1760, b = rem / 55, p = rem % 55;
        xrp = (sub ? x2 : x1) + (size_t)b * 256 * 110 + p;
        int t0 = cell ? 255 : 0;
        xs[tid] = __floats2half2_rn(xrp[(size_t)t0 * 110], xrp[(size_t)t0 * 110 + 55]);
    }
    __syncthreads();

    // B x4-ldmatrix bases: pair P covers nt=2P,2P+1 (16 B-rows)
    uint32_t baddr2[2];
#pragma unroll
    for (int P = 0; P < 2; P++)
        baddr2[P] = smem_u32(Bw + (wid * 32 + P * 16 + ((lane >> 4) * 8) + (lane & 7)) * RS
                                + (((lane >> 3) & 1) * 8));

    uint32_t laneoff = (uint32_t)(((lane & 7) + 8 * ((lane >> 3) & 1)) * RS * 2
                                  + (lane >> 4) * 16);

    const __half2 h05 = __floats2half2_rn(0.5f, 0.5f);
    __half2 cst2[2];
    cst2[0] = __floats2half2_rn(0.f, 0.f);
    cst2[1] = __floats2half2_rn(0.f, 0.f);

    float xn0 = 0.f, xn1 = 0.f;

    for (int t = 0; t < 256; t++) {
        __half*  Ac  = (t & 1) ? A1 : A0;
        __half*  An  = (t & 1) ? A0 : A1;
        __half2* xsc = xs + (t & 1) * 16;
        __half2* xsn = xs + ((t + 1) & 1) * 16;
        uint32_t abase = smem_u32(Ac) + laneoff;

        if (tid < MB && t < 255) {
            int tx = cell ? 254 - t : t + 1;
            xn0 = xrp[(size_t)tx * 110];
            xn1 = xrp[(size_t)tx * 110 + 55];
        }

        // seed accumulators with gx = x0*wxa + x1*wxb + b (per row-pair p)
        uint32_t acc[4][2];
        {
            __half2 xr[2] = { xsc[r0], xsc[r0 + 8] };
#pragma unroll
            for (int p = 0; p < 2; p++) {
                __half2 xx0 = __half2half2(__low2half(xr[p]));
                __half2 xx1 = __half2half2(__high2half(xr[p]));
#pragma unroll
                for (int nt = 0; nt < 4; nt++) {
                    __half2 g = __hfma2(wxa2[nt], xx0, __hfma2(wxb2[nt], xx1, bb2[nt]));
                    acc[nt][p] = *(uint32_t*)&g;
                }
            }
        }

#pragma unroll
        for (int kt = 0; kt < 4; kt++) {
            uint32_t a0, a1, a2, a3;
            asm volatile("ldmatrix.sync.aligned.m8n8.x4.shared.b16 {%0,%1,%2,%3}, [%4];"
                         : "=r"(a0), "=r"(a1), "=r"(a2), "=r"(a3)
                         : "r"(abase + (uint32_t)(kt * 32)));
            uint32_t b0, b1, b2, b3;
            asm volatile("ldmatrix.sync.aligned.m8n8.x4.shared.b16 {%0,%1,%2,%3}, [%4];"
                         : "=r"(b0), "=r"(b1), "=r"(b2), "=r"(b3)
                         : "r"(baddr2[0] + (uint32_t)(kt * 32)));
            MMA16816H(acc[0][0], acc[0][1], a0, a1, a2, a3, b0, b1);
            MMA16816H(acc[1][0], acc[1][1], a0, a1, a2, a3, b2, b3);
            asm volatile("ldmatrix.sync.aligned.m8n8.x4.shared.b16 {%0,%1,%2,%3}, [%4];"
                         : "=r"(b0), "=r"(b1), "=r"(b2), "=r"(b3)
                         : "r"(baddr2[1] + (uint32_t)(kt * 32)));
            MMA16816H(acc[2][0], acc[2][1], a0, a1, a2, a3, b0, b1);
            MMA16816H(acc[3][0], acc[3][1], a0, a1, a2, a3, b2, b3);
        }

        // f16x2 epilogue: p = row (r0 + 8p), chans (ch, ch+1); acc already half2
#pragma unroll
        for (int p = 0; p < 2; p++) {
            __half2 iv = __hfma2(tanh_h2(u2h(acc[0][p])), h05, h05);
            __half2 fv = __hfma2(tanh_h2(u2h(acc[1][p])), h05, h05);
            __half2 ov = __hfma2(tanh_h2(u2h(acc[2][p])), h05, h05);
            __half2 gv = tanh_h2(u2h(acc[3][p]));
            __half2 cn = __hfma2(fv, cst2[p], __hmul2(iv, gv));
            cst2[p] = cn;
            __half2 h2 = __hmul2(ov, tanh_h2(cn));
            *(__half2*)(An + (r0 + p * 8) * RS + ch) = h2;

            if (t == 255) {
                float2 hf = __half22float2(h2);
                int ric = rb + r0 + p * 8;
                int sub = ric / 1760, rem = ric % 1760, bb = rem / 55, pp = rem % 55;
                size_t base = (size_t)(sub * 32 + bb) * 7040 + cell * 3520 + pp;
                feat[base + (size_t)ch * 55]       = hf.x;
                feat[base + (size_t)(ch + 1) * 55] = hf.y;
            }
        }

        if (tid < MB && t < 255)
            xsn[tid] = __floats2half2_rn(xn0, xn1);

        __syncthreads();
    }
}

// ---------------- FC: K-split GEMM partials + reduce ----------------
__global__ __launch_bounds__(256)
void gemm_part(const float* __restrict__ X, const float* __restrict__ W,
               float* __restrict__ Ppart, int N, int K, int KS)
{
    int n0 = blockIdx.x * 64;
    int ks = blockIdx.y;
    int k0s = (int)(((long)K * ks) / KS);
    int k1s = (int)(((long)K * (ks + 1)) / KS);

    __shared__ float Asm[64][17];
    __shared__ float Bsm[16][65];

    int tid = threadIdx.x;
    int nl  = tid & 63;
    int mg  = tid >> 6;

    bool vec_ok = ((N & 3) == 0);

    float acc[16];
#pragma unroll
    for (int i = 0; i < 16; i++) acc[i] = 0.f;

    for (int k0 = k0s; k0 < k1s; k0 += 16) {
#pragma unroll
        for (int i = 0; i < 4; i++) {
            int rr = (tid >> 4) + i * 16;
            int cc = tid & 15;
            int k = k0 + cc;
            Asm[rr][cc] = (k < k1s) ? X[(size_t)rr * K + k] : 0.f;
        }
        {
            int rr = tid >> 4;
            int c4 = (tid & 15) * 4;
            int k  = k0 + rr;
            int nn = n0 + c4;
            if (vec_ok && k < k1s && nn + 3 < N) {
                float4 v = *(const float4*)&W[(size_t)k * N + nn];
                Bsm[rr][c4]     = v.x;
                Bsm[rr][c4 + 1] = v.y;
                Bsm[rr][c4 + 2] = v.z;
                Bsm[rr][c4 + 3] = v.w;
            } else {
#pragma unroll
                for (int e = 0; e < 4; e++)
                    Bsm[rr][c4 + e] = (k < k1s && nn + e < N)
                                      ? W[(size_t)k * N + nn + e] : 0.f;
            }
        }
        __syncthreads();
#pragma unroll
        for (int kk = 0; kk < 16; kk++) {
            float bv = Bsm[kk][nl];
#pragma unroll
            for (int i = 0; i < 16; i++)
                acc[i] += Asm[mg * 16 + i][kk] * bv;
        }
        __syncthreads();
    }

    int nn = n0 + nl;
    if (nn < N) {
        float* outp = Ppart + (size_t)ks * 64 * N;
#pragma unroll
        for (int i = 0; i < 16; i++)
            outp[(size_t)(mg * 16 + i) * N + nn] = acc[i];
    }
}

__global__ void reduce_bias(const float* __restrict__ Ppart, const float* __restrict__ bias,
                            float* __restrict__ Y, int N, int KS)
{
    int idx = blockIdx.x * 256 + threadIdx.x;
    if (idx >= 64 * N) return;
    int nn = idx % N;
    float s = bias[nn];
    for (int ks = 0; ks < KS; ks++) s += Ppart[(size_t)ks * 64 * N + idx];
    Y[idx] = s;
}

// ---------------- launch ----------------
extern "C" void kernel_launch(void* const* d_in, const int* in_sizes, int n_in,
                              void* d_out, int out_size)
{
    const float* x1  = (const float*)d_in[0];
    const float* x2  = (const float*)d_in[1];
    const float* wx1 = (const float*)d_in[2];
    const float* wh1 = (const float*)d_in[3];
    const float* bx1 = (const float*)d_in[4];
    const float* bh1 = (const float*)d_in[5];
    const float* wx2 = (const float*)d_in[6];
    const float* wh2 = (const float*)d_in[7];
    const float* bx2 = (const float*)d_in[8];
    const float* bh2 = (const float*)d_in[9];
    const float* fw2 = (const float*)d_in[10];
    const float* fb2 = (const float*)d_in[11];
    const float* fw3 = (const float*)d_in[12];
    const float* fb3 = (const float*)d_in[13];
    const float* fw4 = (const float*)d_in[14];
    const float* fb4 = (const float*)d_in[15];
    const float* fw5 = (const float*)d_in[16];
    const float* fb5 = (const float*)d_in[17];

    float *feat, *y1, *y2, *y3, *part;
    cudaGetSymbolAddress((void**)&feat, g_feat);
    cudaGetSymbolAddress((void**)&y1,   g_y1);
    cudaGetSymbolAddress((void**)&y2,   g_y2);
    cudaGetSymbolAddress((void**)&y3,   g_y3);
    cudaGetSymbolAddress((void**)&part, g_part);

    cudaFuncSetAttribute(lstm_mma, cudaFuncAttributeMaxDynamicSharedMemorySize, SMEM_BYTES);

    lstm_mma<<<440, 256, SMEM_BYTES>>>(x1, x2, wx1, wh1, bx1, bh1,
                                       wx2, wh2, bx2, bh2, feat);

    // FC1: 7040 -> 3400
    gemm_part<<<dim3(54, 16), 256>>>(feat, fw2, part, 3400, 7040, 16);
    reduce_bias<<<(64 * 3400 + 255) / 256, 256>>>(part, fb2, y1, 3400, 16);
    // FC2: 3400 -> 1000
    gemm_part<<<dim3(16, 8), 256>>>(y1, fw3, part, 1000, 3400, 8);
    reduce_bias<<<(64 * 1000 + 255) / 256, 256>>>(part, fb3, y2, 1000, 8);
    // FC3: 1000 -> 500
    gemm_part<<<dim3(8, 4), 256>>>(y2, fw4, part, 500, 1000, 4);
    reduce_bias<<<(64 * 500 + 255) / 256, 256>>>(part, fb4, y3, 500, 4);
    // FC4: 500 -> 50 -> d_out
    gemm_part<<<dim3(1, 2), 256>>>(y3, fw5, part, 50, 500, 2);
    reduce_bias<<<(64 * 50 + 255) / 256, 256>>>(part, fb5, (float*)d_out, 50, 2);
}

// round 15
// speedup vs baseline: 1.2537x; 1.1454x over previous
#include <cuda_runtime.h>
#include <cuda_fp16.h>
#include <cstdint>

#define RS   88                 // halves per smem row (176 B, conflict-free)
#define MB   16                 // rows per block
#define ASZH (MB * RS)          // halves per A buffer
#define XSOFF (2 * ASZH + 256 * RS)              // half2 x-ring after B (in halves)
#define CSOFF (XSOFF + 64)                       // const LUT (in halves): 32*24 halves
#define SMEM_BYTES ((CSOFF + 32 * 24) * 2)

// ---------------- scratch ----------------
__device__ float g_feat[2 * 32 * 2 * 64 * 55];   // [sub][b][7040]
__device__ float g_y1[64 * 3400];
__device__ float g_y2[64 * 1000];
__device__ float g_y3[64 * 512];
__device__ float g_part[32 * 64 * 3400];

__device__ __forceinline__ __half2 tanh_h2(__half2 x) {
    uint32_t v = *(uint32_t*)&x, r;
    asm("tanh.approx.f16x2 %0, %1;" : "=r"(r) : "r"(v));
    return *(__half2*)&r;
}
__device__ __forceinline__ __half2 u2h(uint32_t v) { return *(__half2*)&v; }

__device__ __forceinline__ uint32_t smem_u32(const void* p) {
    uint32_t a;
    asm("{ .reg .u64 t; cvta.to.shared.u64 t, %1; cvt.u32.u64 %0, t; }" : "=r"(a) : "l"(p));
    return a;
}

// fp16-accumulator HMMA
#define MMA16816H(d0, d1, a0, a1, a2, a3, b0, b1) \
    asm volatile("mma.sync.aligned.m16n8k16.row.col.f16.f16.f16.f16 " \
        "{%0,%1}, {%2,%3,%4,%5}, {%6,%7}, {%0,%1};" \
        : "+r"(d0), "+r"(d1) \
        : "r"(a0), "r"(a1), "r"(a2), "r"(a3), "r"(b0), "r"(b1))

// ---------------- tensor-core LSTM (HMMA f16-accum, K=64, B-in-regs, 3 blocks/SM) ----
// grid = 440: blk/220 = cell, rb = (blk%220)*16.
// Warp w owns B cols [32w,32w+32): col n -> gate (n>>3)&3, channel 8w + (n&7).
// Lane owns rows {lane>>2, +8}, channels {8w+(lane&3)*2, +1}; full gate quad in-lane.
__global__ __launch_bounds__(256, 3)
void lstm_mma(const float* __restrict__ x1, const float* __restrict__ x2,
              const float* __restrict__ wx1, const float* __restrict__ wh1,
              const float* __restrict__ bx1, const float* __restrict__ bh1,
              const float* __restrict__ wx2, const float* __restrict__ wh2,
              const float* __restrict__ bx2, const float* __restrict__ bh2,
              float* __restrict__ feat)
{
    extern __shared__ __align__(16) __half smem[];
    __half*  A0 = smem;
    __half*  A1 = smem + ASZH;
    __half*  Bw = smem + 2 * ASZH;
    __half2* xs = (__half2*)(smem + XSOFF);      // [2][16]
    uint4*   cs = (uint4*)(smem + CSOFF);        // [32][3] : wxa2[4], wxb2[4], bb2[4]

    int tid = threadIdx.x, wid = tid >> 5, lane = tid & 31;
    int blk = blockIdx.x;
    int cell = blk / 220;
    int rb   = (blk % 220) * MB;

    const float* wh = cell ? wh2 : wh1;
    const float* wx = cell ? wx2 : wx1;
    const float* bx = cell ? bx2 : bx1;
    const float* bh = cell ? bh2 : bh1;

    // ---- build B (fp16, 0.5-prescaled for sigmoid gates i,f,o), K=64 ----
    {
        int n  = tid;
        int w  = n >> 5, g = (n >> 3) & 3, cl = n & 7;
        int gc = g * 64 + 8 * w + cl;
        float s = (g == 3) ? 1.0f : 0.5f;
        __half* bp = Bw + n * RS;
#pragma unroll 8
        for (int k = 0; k < 64; k++) bp[k] = __float2half(wh[k * 256 + gc] * s);
#pragma unroll
        for (int k = 64; k < RS; k++) bp[k] = __float2half(0.f);
    }
    // ---- zero A buffers ----
    for (int i = tid; i < (2 * ASZH * 2) / 16; i += 256)
        ((uint4*)smem)[i] = make_uint4(0, 0, 0, 0);

    // ---- gx-seed const LUT: entry wid*4 + c (c = lane&3), channels ch=wid*8+2c ----
    if (lane < 4) {
        int ch = wid * 8 + lane * 2;
        uint32_t v[12];
#pragma unroll
        for (int nt = 0; nt < 4; nt++) {
            float s = (nt == 3) ? 1.0f : 0.5f;
            int g0 = nt * 64 + ch, g1 = g0 + 1;
            __half2 a = __floats2half2_rn(wx[g0] * s,       wx[g1] * s);
            __half2 b = __floats2half2_rn(wx[256 + g0] * s, wx[256 + g1] * s);
            __half2 c2 = __floats2half2_rn((bx[g0] + bh[g0]) * s, (bx[g1] + bh[g1]) * s);
            v[nt] = *(uint32_t*)&a; v[4 + nt] = *(uint32_t*)&b; v[8 + nt] = *(uint32_t*)&c2;
        }
        int e = wid * 4 + lane;
        cs[e * 3 + 0] = make_uint4(v[0], v[1], v[2], v[3]);
        cs[e * 3 + 1] = make_uint4(v[4], v[5], v[6], v[7]);
        cs[e * 3 + 2] = make_uint4(v[8], v[9], v[10], v[11]);
    }
    __syncthreads();

    // per-row x pointer (threads 0..15 own row tid)
    const float* xrp = nullptr;
    if (tid < MB) {
        int ric = rb + tid;
        int sub = ric / 1760, rem = ric % 1760, b = rem / 55, p = rem % 55;
        xrp = (sub ? x2 : x1) + (size_t)b * 256 * 110 + p;
        int t0 = cell ? 255 : 0;
        xs[tid] = __floats2half2_rn(xrp[(size_t)t0 * 110], xrp[(size_t)t0 * 110 + 55]);
    }
    __syncthreads();

    // ---- static B fragments into registers (32 regs) ----
    uint32_t bfr[2][4][4];
    {
        int li = lane;
#pragma unroll
        for (int P = 0; P < 2; P++) {
            uint32_t base = smem_u32(Bw + (wid * 32 + P * 16 + ((li >> 4) * 8) + (li & 7)) * RS
                                        + (((li >> 3) & 1) * 8));
#pragma unroll
            for (int kt = 0; kt < 4; kt++)
                asm volatile("ldmatrix.sync.aligned.m8n8.x4.shared.b16 {%0,%1,%2,%3}, [%4];"
                             : "=r"(bfr[P][kt][0]), "=r"(bfr[P][kt][1]),
                               "=r"(bfr[P][kt][2]), "=r"(bfr[P][kt][3])
                             : "r"(base + (uint32_t)(kt * 32)));
        }
    }

    uint32_t laneoff = (uint32_t)(((lane & 7) + 8 * ((lane >> 3) & 1)) * RS * 2
                                  + (lane >> 4) * 16);
    const uint4* cp = &cs[(wid * 4 + (lane & 3)) * 3];

    const __half2 h05 = __floats2half2_rn(0.5f, 0.5f);
    __half2 cst2[2];
    cst2[0] = __floats2half2_rn(0.f, 0.f);
    cst2[1] = __floats2half2_rn(0.f, 0.f);

    int r0 = lane >> 2;
    int ch = wid * 8 + (lane & 3) * 2;

    float xn0 = 0.f, xn1 = 0.f;

    for (int t = 0; t < 256; t++) {
        __half*  Ac  = (t & 1) ? A1 : A0;
        __half*  An  = (t & 1) ? A0 : A1;
        __half2* xsc = xs + (t & 1) * 16;
        __half2* xsn = xs + ((t + 1) & 1) * 16;
        uint32_t abase = smem_u32(Ac) + laneoff;

        if (tid < MB && t < 255) {
            int tx = cell ? 254 - t : t + 1;
            xn0 = xrp[(size_t)tx * 110];
            xn1 = xrp[(size_t)tx * 110 + 55];
        }

        // seed accumulators with gx = x0*wxa + x1*wxb + b (consts from smem LUT)
        uint32_t acc[4][2];
        {
            uint4 ca = cp[0], cb = cp[1], cc = cp[2];
            const uint32_t* wa = (const uint32_t*)&ca;
            const uint32_t* wb = (const uint32_t*)&cb;
            const uint32_t* bbv = (const uint32_t*)&cc;
            __half2 xr[2] = { xsc[r0], xsc[r0 + 8] };
#pragma unroll
            for (int p = 0; p < 2; p++) {
                __half2 xx0 = __half2half2(__low2half(xr[p]));
                __half2 xx1 = __half2half2(__high2half(xr[p]));
#pragma unroll
                for (int nt = 0; nt < 4; nt++) {
                    __half2 g = __hfma2(u2h(wa[nt]), xx0,
                               __hfma2(u2h(wb[nt]), xx1, u2h(bbv[nt])));
                    acc[nt][p] = *(uint32_t*)&g;
                }
            }
        }

#pragma unroll
        for (int kt = 0; kt < 4; kt++) {
            uint32_t a0, a1, a2, a3;
            asm volatile("ldmatrix.sync.aligned.m8n8.x4.shared.b16 {%0,%1,%2,%3}, [%4];"
                         : "=r"(a0), "=r"(a1), "=r"(a2), "=r"(a3)
                         : "r"(abase + (uint32_t)(kt * 32)));
            MMA16816H(acc[0][0], acc[0][1], a0, a1, a2, a3, bfr[0][kt][0], bfr[0][kt][1]);
            MMA16816H(acc[1][0], acc[1][1], a0, a1, a2, a3, bfr[0][kt][2], bfr[0][kt][3]);
            MMA16816H(acc[2][0], acc[2][1], a0, a1, a2, a3, bfr[1][kt][0], bfr[1][kt][1]);
            MMA16816H(acc[3][0], acc[3][1], a0, a1, a2, a3, bfr[1][kt][2], bfr[1][kt][3]);
        }

        // f16x2 epilogue
#pragma unroll
        for (int p = 0; p < 2; p++) {
            __half2 iv = __hfma2(tanh_h2(u2h(acc[0][p])), h05, h05);
            __half2 fv = __hfma2(tanh_h2(u2h(acc[1][p])), h05, h05);
            __half2 ov = __hfma2(tanh_h2(u2h(acc[2][p])), h05, h05);
            __half2 gv = tanh_h2(u2h(acc[3][p]));
            __half2 cn = __hfma2(fv, cst2[p], __hmul2(iv, gv));
            cst2[p] = cn;
            __half2 h2 = __hmul2(ov, tanh_h2(cn));
            *(__half2*)(An + (r0 + p * 8) * RS + ch) = h2;

            if (t == 255) {
                float2 hf = __half22float2(h2);
                int ric = rb + r0 + p * 8;
                int sub = ric / 1760, rem = ric % 1760, bb = rem / 55, pp = rem % 55;
                size_t base = (size_t)(sub * 32 + bb) * 7040 + cell * 3520 + pp;
                feat[base + (size_t)ch * 55]       = hf.x;
                feat[base + (size_t)(ch + 1) * 55] = hf.y;
            }
        }

        if (tid < MB && t < 255)
            xsn[tid] = __floats2half2_rn(xn0, xn1);

        __syncthreads();
    }
}

// ---------------- FC: K-split GEMM partials + reduce ----------------
__global__ __launch_bounds__(256)
void gemm_part(const float* __restrict__ X, const float* __restrict__ W,
               float* __restrict__ Ppart, int N, int K, int KS)
{
    int n0 = blockIdx.x * 64;
    int ks = blockIdx.y;
    int k0s = (int)(((long)K * ks) / KS);
    int k1s = (int)(((long)K * (ks + 1)) / KS);

    __shared__ float Asm[64][17];
    __shared__ float Bsm[16][65];

    int tid = threadIdx.x;
    int nl  = tid & 63;
    int mg  = tid >> 6;

    bool vec_ok = ((N & 3) == 0);

    float acc[16];
#pragma unroll
    for (int i = 0; i < 16; i++) acc[i] = 0.f;

    for (int k0 = k0s; k0 < k1s; k0 += 16) {
#pragma unroll
        for (int i = 0; i < 4; i++) {
            int rr = (tid >> 4) + i * 16;
            int cc = tid & 15;
            int k = k0 + cc;
            Asm[rr][cc] = (k < k1s) ? X[(size_t)rr * K + k] : 0.f;
        }
        {
            int rr = tid >> 4;
            int c4 = (tid & 15) * 4;
            int k  = k0 + rr;
            int nn = n0 + c4;
            if (vec_ok && k < k1s && nn + 3 < N) {
                float4 v = *(const float4*)&W[(size_t)k * N + nn];
                Bsm[rr][c4]     = v.x;
                Bsm[rr][c4 + 1] = v.y;
                Bsm[rr][c4 + 2] = v.z;
                Bsm[rr][c4 + 3] = v.w;
            } else {
#pragma unroll
                for (int e = 0; e < 4; e++)
                    Bsm[rr][c4 + e] = (k < k1s && nn + e < N)
                                      ? W[(size_t)k * N + nn + e] : 0.f;
            }
        }
        __syncthreads();
#pragma unroll
        for (int kk = 0; kk < 16; kk++) {
            float bv = Bsm[kk][nl];
#pragma unroll
            for (int i = 0; i < 16; i++)
                acc[i] += Asm[mg * 16 + i][kk] * bv;
        }
        __syncthreads();
    }

    int nn = n0 + nl;
    if (nn < N) {
        float* outp = Ppart + (size_t)ks * 64 * N;
#pragma unroll
        for (int i = 0; i < 16; i++)
            outp[(size_t)(mg * 16 + i) * N + nn] = acc[i];
    }
}

__global__ void reduce_bias(const float* __restrict__ Ppart, const float* __restrict__ bias,
                            float* __restrict__ Y, int N, int KS)
{
    int idx = blockIdx.x * 256 + threadIdx.x;
    if (idx >= 64 * N) return;
    int nn = idx % N;
    float s = bias[nn];
    for (int ks = 0; ks < KS; ks++) s += Ppart[(size_t)ks * 64 * N + idx];
    Y[idx] = s;
}

// ---------------- launch ----------------
extern "C" void kernel_launch(void* const* d_in, const int* in_sizes, int n_in,
                              void* d_out, int out_size)
{
    const float* x1  = (const float*)d_in[0];
    const float* x2  = (const float*)d_in[1];
    const float* wx1 = (const float*)d_in[2];
    const float* wh1 = (const float*)d_in[3];
    const float* bx1 = (const float*)d_in[4];
    const float* bh1 = (const float*)d_in[5];
    const float* wx2 = (const float*)d_in[6];
    const float* wh2 = (const float*)d_in[7];
    const float* bx2 = (const float*)d_in[8];
    const float* bh2 = (const float*)d_in[9];
    const float* fw2 = (const float*)d_in[10];
    const float* fb2 = (const float*)d_in[11];
    const float* fw3 = (const float*)d_in[12];
    const float* fb3 = (const float*)d_in[13];
    const float* fw4 = (const float*)d_in[14];
    const float* fb4 = (const float*)d_in[15];
    const float* fw5 = (const float*)d_in[16];
    const float* fb5 = (const float*)d_in[17];

    float *feat, *y1, *y2, *y3, *part;
    cudaGetSymbolAddress((void**)&feat, g_feat);
    cudaGetSymbolAddress((void**)&y1,   g_y1);
    cudaGetSymbolAddress((void**)&y2,   g_y2);
    cudaGetSymbolAddress((void**)&y3,   g_y3);
    cudaGetSymbolAddress((void**)&part, g_part);

    cudaFuncSetAttribute(lstm_mma, cudaFuncAttributeMaxDynamicSharedMemorySize, SMEM_BYTES);

    lstm_mma<<<440, 256, SMEM_BYTES>>>(x1, x2, wx1, wh1, bx1, bh1,
                                       wx2, wh2, bx2, bh2, feat);

    // FC1: 7040 -> 3400  (KS=16, grid 864)
    gemm_part<<<dim3(54, 16), 256>>>(feat, fw2, part, 3400, 7040, 16);
    reduce_bias<<<(64 * 3400 + 255) / 256, 256>>>(part, fb2, y1, 3400, 16);
    // FC2: 3400 -> 1000  (KS=32, grid 512)
    gemm_part<<<dim3(16, 32), 256>>>(y1, fw3, part, 1000, 3400, 32);
    reduce_bias<<<(64 * 1000 + 255) / 256, 256>>>(part, fb3, y2, 1000, 32);
    // FC3: 1000 -> 500   (KS=32, grid 256)
    gemm_part<<<dim3(8, 32), 256>>>(y2, fw4, part, 500, 1000, 32);
    reduce_bias<<<(64 * 500 + 255) / 256, 256>>>(part, fb4, y3, 500, 32);
    // FC4: 500 -> 50     (KS=8)
    gemm_part<<<dim3(1, 8), 256>>>(y3, fw5, part, 50, 500, 8);
    reduce_bias<<<(64 * 50 + 255) / 256, 256>>>(part, fb5, (float*)d_out, 50, 8);
}

// round 16
// speedup vs baseline: 1.5365x; 1.2256x over previous
#include <cuda_runtime.h>
#include <cuda_fp16.h>
#include <cstdint>

#define RS   88                 // halves per smem row (176 B, conflict-free)
#define MB   16                 // rows per block
#define ASZH (MB * RS)          // halves per A buffer
#define XSOFF (2 * ASZH + 256 * RS)              // half2 x-ring after B (in halves)
#define CSOFF (XSOFF + 64)                       // const LUT (in halves): 32*24 halves
#define SMEM_BYTES ((CSOFF + 32 * 24) * 2)

// ---------------- scratch ----------------
__device__ float g_feat[2 * 32 * 2 * 64 * 55];   // [sub][b][7040]
__device__ float g_y1[64 * 3400];
__device__ float g_y2[64 * 1000];
__device__ float g_y3[64 * 512];
__device__ float g_part[32 * 64 * 3400];

__device__ __forceinline__ __half2 tanh_h2(__half2 x) {
    uint32_t v = *(uint32_t*)&x, r;
    asm("tanh.approx.f16x2 %0, %1;" : "=r"(r) : "r"(v));
    return *(__half2*)&r;
}
__device__ __forceinline__ __half2 u2h(uint32_t v) { return *(__half2*)&v; }

__device__ __forceinline__ uint32_t smem_u32(const void* p) {
    uint32_t a;
    asm("{ .reg .u64 t; cvta.to.shared.u64 t, %1; cvt.u32.u64 %0, t; }" : "=r"(a) : "l"(p));
    return a;
}

// fp16-accumulator HMMA
#define MMA16816H(d0, d1, a0, a1, a2, a3, b0, b1) \
    asm volatile("mma.sync.aligned.m16n8k16.row.col.f16.f16.f16.f16 " \
        "{%0,%1}, {%2,%3,%4,%5}, {%6,%7}, {%0,%1};" \
        : "+r"(d0), "+r"(d1) \
        : "r"(a0), "r"(a1), "r"(a2), "r"(a3), "r"(b0), "r"(b1))

// fp32-accumulator HMMA
#define MMA16816F(d, a0, a1, a2, a3, b0, b1) \
    asm volatile("mma.sync.aligned.m16n8k16.row.col.f32.f16.f16.f32 " \
        "{%0,%1,%2,%3}, {%4,%5,%6,%7}, {%8,%9}, {%0,%1,%2,%3};" \
        : "+f"((d)[0]), "+f"((d)[1]), "+f"((d)[2]), "+f"((d)[3]) \
        : "r"(a0), "r"(a1), "r"(a2), "r"(a3), "r"(b0), "r"(b1))

// ---------------- tensor-core LSTM (HMMA f16-accum, K=64, B-in-regs, 3 blocks/SM) ----
__global__ __launch_bounds__(256, 3)
void lstm_mma(const float* __restrict__ x1, const float* __restrict__ x2,
              const float* __restrict__ wx1, const float* __restrict__ wh1,
              const float* __restrict__ bx1, const float* __restrict__ bh1,
              const float* __restrict__ wx2, const float* __restrict__ wh2,
              const float* __restrict__ bx2, const float* __restrict__ bh2,
              float* __restrict__ feat)
{
    extern __shared__ __align__(16) __half smem[];
    __half*  A0 = smem;
    __half*  A1 = smem + ASZH;
    __half*  Bw = smem + 2 * ASZH;
    __half2* xs = (__half2*)(smem + XSOFF);      // [2][16]
    uint4*   cs = (uint4*)(smem + CSOFF);        // [32][3]

    int tid = threadIdx.x, wid = tid >> 5, lane = tid & 31;
    int blk = blockIdx.x;
    int cell = blk / 220;
    int rb   = (blk % 220) * MB;

    const float* wh = cell ? wh2 : wh1;
    const float* wx = cell ? wx2 : wx1;
    const float* bx = cell ? bx2 : bx1;
    const float* bh = cell ? bh2 : bh1;

    {
        int n  = tid;
        int w  = n >> 5, g = (n >> 3) & 3, cl = n & 7;
        int gc = g * 64 + 8 * w + cl;
        float s = (g == 3) ? 1.0f : 0.5f;
        __half* bp = Bw + n * RS;
#pragma unroll 8
        for (int k = 0; k < 64; k++) bp[k] = __float2half(wh[k * 256 + gc] * s);
#pragma unroll
        for (int k = 64; k < RS; k++) bp[k] = __float2half(0.f);
    }
    for (int i = tid; i < (2 * ASZH * 2) / 16; i += 256)
        ((uint4*)smem)[i] = make_uint4(0, 0, 0, 0);

    if (lane < 4) {
        int ch = wid * 8 + lane * 2;
        uint32_t v[12];
#pragma unroll
        for (int nt = 0; nt < 4; nt++) {
            float s = (nt == 3) ? 1.0f : 0.5f;
            int g0 = nt * 64 + ch, g1 = g0 + 1;
            __half2 a = __floats2half2_rn(wx[g0] * s,       wx[g1] * s);
            __half2 b = __floats2half2_rn(wx[256 + g0] * s, wx[256 + g1] * s);
            __half2 c2 = __floats2half2_rn((bx[g0] + bh[g0]) * s, (bx[g1] + bh[g1]) * s);
            v[nt] = *(uint32_t*)&a; v[4 + nt] = *(uint32_t*)&b; v[8 + nt] = *(uint32_t*)&c2;
        }
        int e = wid * 4 + lane;
        cs[e * 3 + 0] = make_uint4(v[0], v[1], v[2], v[3]);
        cs[e * 3 + 1] = make_uint4(v[4], v[5], v[6], v[7]);
        cs[e * 3 + 2] = make_uint4(v[8], v[9], v[10], v[11]);
    }
    __syncthreads();

    const float* xrp = nullptr;
    if (tid < MB) {
        int ric = rb + tid;
        int sub = ric / 1760, rem = ric % 1760, b = rem / 55, p = rem % 55;
        xrp = (sub ? x2 : x1) + (size_t)b * 256 * 110 + p;
        int t0 = cell ? 255 : 0;
        xs[tid] = __floats2half2_rn(xrp[(size_t)t0 * 110], xrp[(size_t)t0 * 110 + 55]);
    }
    __syncthreads();

    uint32_t bfr[2][4][4];
    {
        int li = lane;
#pragma unroll
        for (int P = 0; P < 2; P++) {
            uint32_t base = smem_u32(Bw + (wid * 32 + P * 16 + ((li >> 4) * 8) + (li & 7)) * RS
                                        + (((li >> 3) & 1) * 8));
#pragma unroll
            for (int kt = 0; kt < 4; kt++)
                asm volatile("ldmatrix.sync.aligned.m8n8.x4.shared.b16 {%0,%1,%2,%3}, [%4];"
                             : "=r"(bfr[P][kt][0]), "=r"(bfr[P][kt][1]),
                               "=r"(bfr[P][kt][2]), "=r"(bfr[P][kt][3])
                             : "r"(base + (uint32_t)(kt * 32)));
        }
    }

    uint32_t laneoff = (uint32_t)(((lane & 7) + 8 * ((lane >> 3) & 1)) * RS * 2
                                  + (lane >> 4) * 16);
    const uint4* cp = &cs[(wid * 4 + (lane & 3)) * 3];

    const __half2 h05 = __floats2half2_rn(0.5f, 0.5f);
    __half2 cst2[2];
    cst2[0] = __floats2half2_rn(0.f, 0.f);
    cst2[1] = __floats2half2_rn(0.f, 0.f);

    int r0 = lane >> 2;
    int ch = wid * 8 + (lane & 3) * 2;

    float xn0 = 0.f, xn1 = 0.f;

    for (int t = 0; t < 256; t++) {
        __half*  Ac  = (t & 1) ? A1 : A0;
        __half*  An  = (t & 1) ? A0 : A1;
        __half2* xsc = xs + (t & 1) * 16;
        __half2* xsn = xs + ((t + 1) & 1) * 16;
        uint32_t abase = smem_u32(Ac) + laneoff;

        if (tid < MB && t < 255) {
            int tx = cell ? 254 - t : t + 1;
            xn0 = xrp[(size_t)tx * 110];
            xn1 = xrp[(size_t)tx * 110 + 55];
        }

        uint32_t acc[4][2];
        {
            uint4 ca = cp[0], cb = cp[1], cc = cp[2];
            const uint32_t* wa = (const uint32_t*)&ca;
            const uint32_t* wb = (const uint32_t*)&cb;
            const uint32_t* bbv = (const uint32_t*)&cc;
            __half2 xr[2] = { xsc[r0], xsc[r0 + 8] };
#pragma unroll
            for (int p = 0; p < 2; p++) {
                __half2 xx0 = __half2half2(__low2half(xr[p]));
                __half2 xx1 = __half2half2(__high2half(xr[p]));
#pragma unroll
                for (int nt = 0; nt < 4; nt++) {
                    __half2 g = __hfma2(u2h(wa[nt]), xx0,
                               __hfma2(u2h(wb[nt]), xx1, u2h(bbv[nt])));
                    acc[nt][p] = *(uint32_t*)&g;
                }
            }
        }

#pragma unroll
        for (int kt = 0; kt < 4; kt++) {
            uint32_t a0, a1, a2, a3;
            asm volatile("ldmatrix.sync.aligned.m8n8.x4.shared.b16 {%0,%1,%2,%3}, [%4];"
                         : "=r"(a0), "=r"(a1), "=r"(a2), "=r"(a3)
                         : "r"(abase + (uint32_t)(kt * 32)));
            MMA16816H(acc[0][0], acc[0][1], a0, a1, a2, a3, bfr[0][kt][0], bfr[0][kt][1]);
            MMA16816H(acc[1][0], acc[1][1], a0, a1, a2, a3, bfr[0][kt][2], bfr[0][kt][3]);
            MMA16816H(acc[2][0], acc[2][1], a0, a1, a2, a3, bfr[1][kt][0], bfr[1][kt][1]);
            MMA16816H(acc[3][0], acc[3][1], a0, a1, a2, a3, bfr[1][kt][2], bfr[1][kt][3]);
        }

#pragma unroll
        for (int p = 0; p < 2; p++) {
            __half2 iv = __hfma2(tanh_h2(u2h(acc[0][p])), h05, h05);
            __half2 fv = __hfma2(tanh_h2(u2h(acc[1][p])), h05, h05);
            __half2 ov = __hfma2(tanh_h2(u2h(acc[2][p])), h05, h05);
            __half2 gv = tanh_h2(u2h(acc[3][p]));
            __half2 cn = __hfma2(fv, cst2[p], __hmul2(iv, gv));
            cst2[p] = cn;
            __half2 h2 = __hmul2(ov, tanh_h2(cn));
            *(__half2*)(An + (r0 + p * 8) * RS + ch) = h2;

            if (t == 255) {
                float2 hf = __half22float2(h2);
                int ric = rb + r0 + p * 8;
                int sub = ric / 1760, rem = ric % 1760, bb = rem / 55, pp = rem % 55;
                size_t base = (size_t)(sub * 32 + bb) * 7040 + cell * 3520 + pp;
                feat[base + (size_t)ch * 55]       = hf.x;
                feat[base + (size_t)(ch + 1) * 55] = hf.y;
            }
        }

        if (tid < MB && t < 255)
            xsn[tid] = __floats2half2_rn(xn0, xn1);

        __syncthreads();
    }
}

// ---------------- FC1: fp16 HMMA K-split GEMM (in-kernel conversion) ----------------
// Block computes 64 rows x 64 cols for one k-slice. Warp (rq=wid&3, cw=wid>>2)
// owns rows [16rq,16rq+16), cols [32cw,32cw+32).
__global__ __launch_bounds__(256)
void gemm16_part(const float* __restrict__ X, const float* __restrict__ W,
                 float* __restrict__ Ppart, int N, int K, int KS)
{
    __shared__ __half As[64][24];   // [row][k]
    __shared__ __half Bs[64][24];   // [col][k]

    int n0 = blockIdx.x * 64;
    int ks = blockIdx.y;
    int KC = (((K + KS - 1) / KS + 15) >> 4) << 4;   // k-slice, multiple of 16
    int k0s = ks * KC;
    int k1s = min(K, k0s + KC);

    int tid = threadIdx.x, wid = tid >> 5, lane = tid & 31;
    int rq = wid & 3, cw = wid >> 2;

    float acc[4][4];
#pragma unroll
    for (int i = 0; i < 4; i++)
#pragma unroll
        for (int j = 0; j < 4; j++) acc[i][j] = 0.f;

    uint32_t aaddr = smem_u32(&As[rq * 16 + (lane & 15)][(lane >> 4) * 8]);
    uint32_t baddr[2];
#pragma unroll
    for (int P = 0; P < 2; P++)
        baddr[P] = smem_u32(&Bs[cw * 32 + P * 16 + ((lane >> 4) * 8) + (lane & 7)]
                               [((lane >> 3) & 1) * 8]);

    for (int k0 = k0s; k0 < k1s; k0 += 16) {
        // A tile: 64 x 16 f32 -> fp16
        {
            int row = tid >> 2, kkb = (tid & 3) * 4;
            int k = k0 + kkb;
            float4 v = make_float4(0.f, 0.f, 0.f, 0.f);
            if (k + 3 < k1s) v = *(const float4*)&X[(size_t)row * K + k];
            else {
                if (k     < k1s) v.x = X[(size_t)row * K + k];
                if (k + 1 < k1s) v.y = X[(size_t)row * K + k + 1];
                if (k + 2 < k1s) v.z = X[(size_t)row * K + k + 2];
                if (k + 3 < k1s) v.w = X[(size_t)row * K + k + 3];
            }
            __half2 h0 = __floats2half2_rn(v.x, v.y);
            __half2 h1 = __floats2half2_rn(v.z, v.w);
            uint2 u = make_uint2(*(uint32_t*)&h0, *(uint32_t*)&h1);
            *(uint2*)&As[row][kkb] = u;
        }
        // B tile: 16 x 64 f32 -> fp16 transposed to [col][k]
        {
            int kk = tid >> 4, c4 = (tid & 15) * 4;
            int k = k0 + kk, nn = n0 + c4;
            float4 v = make_float4(0.f, 0.f, 0.f, 0.f);
            if (k < k1s) {
                if (nn + 3 < N) v = *(const float4*)&W[(size_t)k * N + nn];
                else {
                    if (nn     < N) v.x = W[(size_t)k * N + nn];
                    if (nn + 1 < N) v.y = W[(size_t)k * N + nn + 1];
                    if (nn + 2 < N) v.z = W[(size_t)k * N + nn + 2];
                    if (nn + 3 < N) v.w = W[(size_t)k * N + nn + 3];
                }
            }
            Bs[c4 + 0][kk] = __float2half(v.x);
            Bs[c4 + 1][kk] = __float2half(v.y);
            Bs[c4 + 2][kk] = __float2half(v.z);
            Bs[c4 + 3][kk] = __float2half(v.w);
        }
        __syncthreads();

        uint32_t a0, a1, a2, a3;
        asm volatile("ldmatrix.sync.aligned.m8n8.x4.shared.b16 {%0,%1,%2,%3}, [%4];"
                     : "=r"(a0), "=r"(a1), "=r"(a2), "=r"(a3) : "r"(aaddr));
#pragma unroll
        for (int P = 0; P < 2; P++) {
            uint32_t b0, b1, b2, b3;
            asm volatile("ldmatrix.sync.aligned.m8n8.x4.shared.b16 {%0,%1,%2,%3}, [%4];"
                         : "=r"(b0), "=r"(b1), "=r"(b2), "=r"(b3) : "r"(baddr[P]));
            MMA16816F(acc[2 * P],     a0, a1, a2, a3, b0, b1);
            MMA16816F(acc[2 * P + 1], a0, a1, a2, a3, b2, b3);
        }
        __syncthreads();
    }

    // write partials: acc[nt][j]: rows rq*16 + lane>>2 (+8 for j>=2), col nt*8 + (lane&3)*2 (+1)
    int row = rq * 16 + (lane >> 2);
    int colb = cw * 32 + (lane & 3) * 2;
    float* outp = Ppart + (size_t)ks * 64 * N;
#pragma unroll
    for (int nt = 0; nt < 4; nt++) {
#pragma unroll
        for (int pr = 0; pr < 2; pr++) {
            int r = row + pr * 8;
            int c = n0 + colb + nt * 8;
            if (c < N)     outp[(size_t)r * N + c]     = acc[nt][pr * 2 + 0];
            if (c + 1 < N) outp[(size_t)r * N + c + 1] = acc[nt][pr * 2 + 1];
        }
    }
}

// ---------------- FC: scalar K-split GEMM partials + reduce (FC2-4) ----------------
__global__ __launch_bounds__(256)
void gemm_part(const float* __restrict__ X, const float* __restrict__ W,
               float* __restrict__ Ppart, int N, int K, int KS)
{
    int n0 = blockIdx.x * 64;
    int ks = blockIdx.y;
    int k0s = (int)(((long)K * ks) / KS);
    int k1s = (int)(((long)K * (ks + 1)) / KS);

    __shared__ float Asm[64][17];
    __shared__ float Bsm[16][65];

    int tid = threadIdx.x;
    int nl  = tid & 63;
    int mg  = tid >> 6;

    bool vec_ok = ((N & 3) == 0);

    float acc[16];
#pragma unroll
    for (int i = 0; i < 16; i++) acc[i] = 0.f;

    for (int k0 = k0s; k0 < k1s; k0 += 16) {
#pragma unroll
        for (int i = 0; i < 4; i++) {
            int rr = (tid >> 4) + i * 16;
            int cc = tid & 15;
            int k = k0 + cc;
            Asm[rr][cc] = (k < k1s) ? X[(size_t)rr * K + k] : 0.f;
        }
        {
            int rr = tid >> 4;
            int c4 = (tid & 15) * 4;
            int k  = k0 + rr;
            int nn = n0 + c4;
            if (vec_ok && k < k1s && nn + 3 < N) {
                float4 v = *(const float4*)&W[(size_t)k * N + nn];
                Bsm[rr][c4]     = v.x;
                Bsm[rr][c4 + 1] = v.y;
                Bsm[rr][c4 + 2] = v.z;
                Bsm[rr][c4 + 3] = v.w;
            } else {
#pragma unroll
                for (int e = 0; e < 4; e++)
                    Bsm[rr][c4 + e] = (k < k1s && nn + e < N)
                                      ? W[(size_t)k * N + nn + e] : 0.f;
            }
        }
        __syncthreads();
#pragma unroll
        for (int kk = 0; kk < 16; kk++) {
            float bv = Bsm[kk][nl];
#pragma unroll
            for (int i = 0; i < 16; i++)
                acc[i] += Asm[mg * 16 + i][kk] * bv;
        }
        __syncthreads();
    }

    int nn = n0 + nl;
    if (nn < N) {
        float* outp = Ppart + (size_t)ks * 64 * N;
#pragma unroll
        for (int i = 0; i < 16; i++)
            outp[(size_t)(mg * 16 + i) * N + nn] = acc[i];
    }
}

__global__ void reduce_bias(const float* __restrict__ Ppart, const float* __restrict__ bias,
                            float* __restrict__ Y, int N, int KS)
{
    int idx = blockIdx.x * 256 + threadIdx.x;
    if (idx >= 64 * N) return;
    int nn = idx % N;
    float s = bias[nn];
    for (int ks = 0; ks < KS; ks++) s += Ppart[(size_t)ks * 64 * N + idx];
    Y[idx] = s;
}

// ---------------- launch ----------------
extern "C" void kernel_launch(void* const* d_in, const int* in_sizes, int n_in,
                              void* d_out, int out_size)
{
    const float* x1  = (const float*)d_in[0];
    const float* x2  = (const float*)d_in[1];
    const float* wx1 = (const float*)d_in[2];
    const float* wh1 = (const float*)d_in[3];
    const float* bx1 = (const float*)d_in[4];
    const float* bh1 = (const float*)d_in[5];
    const float* wx2 = (const float*)d_in[6];
    const float* wh2 = (const float*)d_in[7];
    const float* bx2 = (const float*)d_in[8];
    const float* bh2 = (const float*)d_in[9];
    const float* fw2 = (const float*)d_in[10];
    const float* fb2 = (const float*)d_in[11];
    const float* fw3 = (const float*)d_in[12];
    const float* fb3 = (const float*)d_in[13];
    const float* fw4 = (const float*)d_in[14];
    const float* fb4 = (const float*)d_in[15];
    const float* fw5 = (const float*)d_in[16];
    const float* fb5 = (const float*)d_in[17];

    float *feat, *y1, *y2, *y3, *part;
    cudaGetSymbolAddress((void**)&feat, g_feat);
    cudaGetSymbolAddress((void**)&y1,   g_y1);
    cudaGetSymbolAddress((void**)&y2,   g_y2);
    cudaGetSymbolAddress((void**)&y3,   g_y3);
    cudaGetSymbolAddress((void**)&part, g_part);

    cudaFuncSetAttribute(lstm_mma, cudaFuncAttributeMaxDynamicSharedMemorySize, SMEM_BYTES);

    lstm_mma<<<440, 256, SMEM_BYTES>>>(x1, x2, wx1, wh1, bx1, bh1,
                                       wx2, wh2, bx2, bh2, feat);

    // FC1: 7040 -> 3400  (fp16 HMMA, KS=16, grid 54x16)
    gemm16_part<<<dim3(54, 16), 256>>>(feat, fw2, part, 3400, 7040, 16);
    reduce_bias<<<(64 * 3400 + 255) / 256, 256>>>(part, fb2, y1, 3400, 16);
    // FC2: 3400 -> 1000  (KS=64, grid 1024)
    gemm_part<<<dim3(16, 64), 256>>>(y1, fw3, part, 1000, 3400, 64);
    reduce_bias<<<(64 * 1000 + 255) / 256, 256>>>(part, fb3, y2, 1000, 64);
    // FC3: 1000 -> 500   (KS=32, grid 256)
    gemm_part<<<dim3(8, 32), 256>>>(y2, fw4, part, 500, 1000, 32);
    reduce_bias<<<(64 * 500 + 255) / 256, 256>>>(part, fb4, y3, 500, 32);
    // FC4: 500 -> 50     (KS=8)
    gemm_part<<<dim3(1, 8), 256>>>(y3, fw5, part, 50, 500, 8);
    reduce_bias<<<(64 * 50 + 255) / 256, 256>>>(part, fb5, (float*)d_out, 50, 8);
}

// round 17
// speedup vs baseline: 1.6401x; 1.0674x over previous
#include <cuda_runtime.h>
#include <cuda_fp16.h>
#include <cstdint>

#define RS   88                 // halves per smem row (176 B, conflict-free)
#define MB   16                 // rows per block
#define ASZH (MB * RS)          // halves per A buffer
#define XSOFF (2 * ASZH + 256 * RS)              // half2 x-ring after B (in halves)
#define CSOFF (XSOFF + 64)                       // const LUT (in halves): 32*24 halves
#define SMEM_BYTES ((CSOFF + 32 * 24) * 2)

// ---------------- scratch ----------------
__device__ float g_feat[2 * 32 * 2 * 64 * 55];   // [sub][b][7040]
__device__ float g_y1[64 * 3400];
__device__ float g_y2[64 * 1000];
__device__ float g_y3[64 * 512];
__device__ float g_part[32 * 64 * 3400];

__device__ __forceinline__ __half2 tanh_h2(__half2 x) {
    uint32_t v = *(uint32_t*)&x, r;
    asm("tanh.approx.f16x2 %0, %1;" : "=r"(r) : "r"(v));
    return *(__half2*)&r;
}
__device__ __forceinline__ __half2 u2h(uint32_t v) { return *(__half2*)&v; }

__device__ __forceinline__ uint32_t smem_u32(const void* p) {
    uint32_t a;
    asm("{ .reg .u64 t; cvta.to.shared.u64 t, %1; cvt.u32.u64 %0, t; }" : "=r"(a) : "l"(p));
    return a;
}

// fp16-accumulator HMMA
#define MMA16816H(d0, d1, a0, a1, a2, a3, b0, b1) \
    asm volatile("mma.sync.aligned.m16n8k16.row.col.f16.f16.f16.f16 " \
        "{%0,%1}, {%2,%3,%4,%5}, {%6,%7}, {%0,%1};" \
        : "+r"(d0), "+r"(d1) \
        : "r"(a0), "r"(a1), "r"(a2), "r"(a3), "r"(b0), "r"(b1))

// fp32-accumulator HMMA
#define MMA16816F(d, a0, a1, a2, a3, b0, b1) \
    asm volatile("mma.sync.aligned.m16n8k16.row.col.f32.f16.f16.f32 " \
        "{%0,%1,%2,%3}, {%4,%5,%6,%7}, {%8,%9}, {%0,%1,%2,%3};" \
        : "+f"((d)[0]), "+f"((d)[1]), "+f"((d)[2]), "+f"((d)[3]) \
        : "r"(a0), "r"(a1), "r"(a2), "r"(a3), "r"(b0), "r"(b1))

// ---------------- tensor-core LSTM (HMMA f16-accum, K=64, B-in-regs, 3 blocks/SM) ----
__global__ __launch_bounds__(256, 3)
void lstm_mma(const float* __restrict__ x1, const float* __restrict__ x2,
              const float* __restrict__ wx1, const float* __restrict__ wh1,
              const float* __restrict__ bx1, const float* __restrict__ bh1,
              const float* __restrict__ wx2, const float* __restrict__ wh2,
              const float* __restrict__ bx2, const float* __restrict__ bh2,
              float* __restrict__ feat)
{
    extern __shared__ __align__(16) __half smem[];
    __half*  A0 = smem;
    __half*  A1 = smem + ASZH;
    __half*  Bw = smem + 2 * ASZH;
    __half2* xs = (__half2*)(smem + XSOFF);      // [2][16]
    uint4*   cs = (uint4*)(smem + CSOFF);        // [32][3]

    int tid = threadIdx.x, wid = tid >> 5, lane = tid & 31;
    int blk = blockIdx.x;
    int cell = blk / 220;
    int rb   = (blk % 220) * MB;

    const float* wh = cell ? wh2 : wh1;
    const float* wx = cell ? wx2 : wx1;
    const float* bx = cell ? bx2 : bx1;
    const float* bh = cell ? bh2 : bh1;

    {
        int n  = tid;
        int w  = n >> 5, g = (n >> 3) & 3, cl = n & 7;
        int gc = g * 64 + 8 * w + cl;
        float s = (g == 3) ? 1.0f : 0.5f;
        __half* bp = Bw + n * RS;
#pragma unroll 8
        for (int k = 0; k < 64; k++) bp[k] = __float2half(wh[k * 256 + gc] * s);
#pragma unroll
        for (int k = 64; k < RS; k++) bp[k] = __float2half(0.f);
    }
    for (int i = tid; i < (2 * ASZH * 2) / 16; i += 256)
        ((uint4*)smem)[i] = make_uint4(0, 0, 0, 0);

    if (lane < 4) {
        int ch = wid * 8 + lane * 2;
        uint32_t v[12];
#pragma unroll
        for (int nt = 0; nt < 4; nt++) {
            float s = (nt == 3) ? 1.0f : 0.5f;
            int g0 = nt * 64 + ch, g1 = g0 + 1;
            __half2 a = __floats2half2_rn(wx[g0] * s,       wx[g1] * s);
            __half2 b = __floats2half2_rn(wx[256 + g0] * s, wx[256 + g1] * s);
            __half2 c2 = __floats2half2_rn((bx[g0] + bh[g0]) * s, (bx[g1] + bh[g1]) * s);
            v[nt] = *(uint32_t*)&a; v[4 + nt] = *(uint32_t*)&b; v[8 + nt] = *(uint32_t*)&c2;
        }
        int e = wid * 4 + lane;
        cs[e * 3 + 0] = make_uint4(v[0], v[1], v[2], v[3]);
        cs[e * 3 + 1] = make_uint4(v[4], v[5], v[6], v[7]);
        cs[e * 3 + 2] = make_uint4(v[8], v[9], v[10], v[11]);
    }
    __syncthreads();

    const float* xrp = nullptr;
    if (tid < MB) {
        int ric = rb + tid;
        int sub = ric / 1760, rem = ric % 1760, b = rem / 55, p = rem % 55;
        xrp = (sub ? x2 : x1) + (size_t)b * 256 * 110 + p;
        int t0 = cell ? 255 : 0;
        xs[tid] = __floats2half2_rn(xrp[(size_t)t0 * 110], xrp[(size_t)t0 * 110 + 55]);
    }
    __syncthreads();

    uint32_t bfr[2][4][4];
    {
        int li = lane;
#pragma unroll
        for (int P = 0; P < 2; P++) {
            uint32_t base = smem_u32(Bw + (wid * 32 + P * 16 + ((li >> 4) * 8) + (li & 7)) * RS
                                        + (((li >> 3) & 1) * 8));
#pragma unroll
            for (int kt = 0; kt < 4; kt++)
                asm volatile("ldmatrix.sync.aligned.m8n8.x4.shared.b16 {%0,%1,%2,%3}, [%4];"
                             : "=r"(bfr[P][kt][0]), "=r"(bfr[P][kt][1]),
                               "=r"(bfr[P][kt][2]), "=r"(bfr[P][kt][3])
                             : "r"(base + (uint32_t)(kt * 32)));
        }
    }

    uint32_t laneoff = (uint32_t)(((lane & 7) + 8 * ((lane >> 3) & 1)) * RS * 2
                                  + (lane >> 4) * 16);
    const uint4* cp = &cs[(wid * 4 + (lane & 3)) * 3];

    const __half2 h05 = __floats2half2_rn(0.5f, 0.5f);
    __half2 cst2[2];
    cst2[0] = __floats2half2_rn(0.f, 0.f);
    cst2[1] = __floats2half2_rn(0.f, 0.f);

    int r0 = lane >> 2;
    int ch = wid * 8 + (lane & 3) * 2;

    float xn0 = 0.f, xn1 = 0.f;

    for (int t = 0; t < 256; t++) {
        __half*  Ac  = (t & 1) ? A1 : A0;
        __half*  An  = (t & 1) ? A0 : A1;
        __half2* xsc = xs + (t & 1) * 16;
        __half2* xsn = xs + ((t + 1) & 1) * 16;
        uint32_t abase = smem_u32(Ac) + laneoff;

        if (tid < MB && t < 255) {
            int tx = cell ? 254 - t : t + 1;
            xn0 = xrp[(size_t)tx * 110];
            xn1 = xrp[(size_t)tx * 110 + 55];
        }

        uint32_t acc[4][2];
        {
            uint4 ca = cp[0], cb = cp[1], cc = cp[2];
            const uint32_t* wa = (const uint32_t*)&ca;
            const uint32_t* wb = (const uint32_t*)&cb;
            const uint32_t* bbv = (const uint32_t*)&cc;
            __half2 xr[2] = { xsc[r0], xsc[r0 + 8] };
#pragma unroll
            for (int p = 0; p < 2; p++) {
                __half2 xx0 = __half2half2(__low2half(xr[p]));
                __half2 xx1 = __half2half2(__high2half(xr[p]));
#pragma unroll
                for (int nt = 0; nt < 4; nt++) {
                    __half2 g = __hfma2(u2h(wa[nt]), xx0,
                               __hfma2(u2h(wb[nt]), xx1, u2h(bbv[nt])));
                    acc[nt][p] = *(uint32_t*)&g;
                }
            }
        }

#pragma unroll
        for (int kt = 0; kt < 4; kt++) {
            uint32_t a0, a1, a2, a3;
            asm volatile("ldmatrix.sync.aligned.m8n8.x4.shared.b16 {%0,%1,%2,%3}, [%4];"
                         : "=r"(a0), "=r"(a1), "=r"(a2), "=r"(a3)
                         : "r"(abase + (uint32_t)(kt * 32)));
            MMA16816H(acc[0][0], acc[0][1], a0, a1, a2, a3, bfr[0][kt][0], bfr[0][kt][1]);
            MMA16816H(acc[1][0], acc[1][1], a0, a1, a2, a3, bfr[0][kt][2], bfr[0][kt][3]);
            MMA16816H(acc[2][0], acc[2][1], a0, a1, a2, a3, bfr[1][kt][0], bfr[1][kt][1]);
            MMA16816H(acc[3][0], acc[3][1], a0, a1, a2, a3, bfr[1][kt][2], bfr[1][kt][3]);
        }

#pragma unroll
        for (int p = 0; p < 2; p++) {
            __half2 iv = __hfma2(tanh_h2(u2h(acc[0][p])), h05, h05);
            __half2 fv = __hfma2(tanh_h2(u2h(acc[1][p])), h05, h05);
            __half2 ov = __hfma2(tanh_h2(u2h(acc[2][p])), h05, h05);
            __half2 gv = tanh_h2(u2h(acc[3][p]));
            __half2 cn = __hfma2(fv, cst2[p], __hmul2(iv, gv));
            cst2[p] = cn;
            __half2 h2 = __hmul2(ov, tanh_h2(cn));
            *(__half2*)(An + (r0 + p * 8) * RS + ch) = h2;

            if (t == 255) {
                float2 hf = __half22float2(h2);
                int ric = rb + r0 + p * 8;
                int sub = ric / 1760, rem = ric % 1760, bb = rem / 55, pp = rem % 55;
                size_t base = (size_t)(sub * 32 + bb) * 7040 + cell * 3520 + pp;
                feat[base + (size_t)ch * 55]       = hf.x;
                feat[base + (size_t)(ch + 1) * 55] = hf.y;
            }
        }

        if (tid < MB && t < 255)
            xsn[tid] = __floats2half2_rn(xn0, xn1);

        __syncthreads();
    }
}

// ---------------- FC: fp16 HMMA K-split GEMM (in-kernel conversion) ----------------
// Block computes 64 rows x 64 cols for one k-slice. Warp (rq=wid&3, cw=wid>>2)
// owns rows [16rq,16rq+16), cols [32cw,32cw+32).
__global__ __launch_bounds__(256)
void gemm16_part(const float* __restrict__ X, const float* __restrict__ W,
                 float* __restrict__ Ppart, int N, int K, int KS)
{
    __shared__ __half As[64][24];   // [row][k]
    __shared__ __half Bs[64][24];   // [col][k]

    int n0 = blockIdx.x * 64;
    int ks = blockIdx.y;
    int KC = (((K + KS - 1) / KS + 15) >> 4) << 4;   // k-slice, multiple of 16
    int k0s = ks * KC;
    int k1s = min(K, k0s + KC);

    int tid = threadIdx.x, wid = tid >> 5, lane = tid & 31;
    int rq = wid & 3, cw = wid >> 2;

    float acc[4][4];
#pragma unroll
    for (int i = 0; i < 4; i++)
#pragma unroll
        for (int j = 0; j < 4; j++) acc[i][j] = 0.f;

    uint32_t aaddr = smem_u32(&As[rq * 16 + (lane & 15)][(lane >> 4) * 8]);
    uint32_t baddr[2];
#pragma unroll
    for (int P = 0; P < 2; P++)
        baddr[P] = smem_u32(&Bs[cw * 32 + P * 16 + ((lane >> 4) * 8) + (lane & 7)]
                               [((lane >> 3) & 1) * 8]);

    for (int k0 = k0s; k0 < k1s; k0 += 16) {
        // A tile: 64 x 16 f32 -> fp16
        {
            int row = tid >> 2, kkb = (tid & 3) * 4;
            int k = k0 + kkb;
            float4 v = make_float4(0.f, 0.f, 0.f, 0.f);
            if (k + 3 < k1s) v = *(const float4*)&X[(size_t)row * K + k];
            else {
                if (k     < k1s) v.x = X[(size_t)row * K + k];
                if (k + 1 < k1s) v.y = X[(size_t)row * K + k + 1];
                if (k + 2 < k1s) v.z = X[(size_t)row * K + k + 2];
                if (k + 3 < k1s) v.w = X[(size_t)row * K + k + 3];
            }
            __half2 h0 = __floats2half2_rn(v.x, v.y);
            __half2 h1 = __floats2half2_rn(v.z, v.w);
            uint2 u = make_uint2(*(uint32_t*)&h0, *(uint32_t*)&h1);
            *(uint2*)&As[row][kkb] = u;
        }
        // B tile: 16 x 64 f32 -> fp16 transposed to [col][k]
        {
            int kk = tid >> 4, c4 = (tid & 15) * 4;
            int k = k0 + kk, nn = n0 + c4;
            float4 v = make_float4(0.f, 0.f, 0.f, 0.f);
            if (k < k1s) {
                if (nn + 3 < N) v = *(const float4*)&W[(size_t)k * N + nn];
                else {
                    if (nn     < N) v.x = W[(size_t)k * N + nn];
                    if (nn + 1 < N) v.y = W[(size_t)k * N + nn + 1];
                    if (nn + 2 < N) v.z = W[(size_t)k * N + nn + 2];
                    if (nn + 3 < N) v.w = W[(size_t)k * N + nn + 3];
                }
            }
            Bs[c4 + 0][kk] = __float2half(v.x);
            Bs[c4 + 1][kk] = __float2half(v.y);
            Bs[c4 + 2][kk] = __float2half(v.z);
            Bs[c4 + 3][kk] = __float2half(v.w);
        }
        __syncthreads();

        uint32_t a0, a1, a2, a3;
        asm volatile("ldmatrix.sync.aligned.m8n8.x4.shared.b16 {%0,%1,%2,%3}, [%4];"
                     : "=r"(a0), "=r"(a1), "=r"(a2), "=r"(a3) : "r"(aaddr));
#pragma unroll
        for (int P = 0; P < 2; P++) {
            uint32_t b0, b1, b2, b3;
            asm volatile("ldmatrix.sync.aligned.m8n8.x4.shared.b16 {%0,%1,%2,%3}, [%4];"
                         : "=r"(b0), "=r"(b1), "=r"(b2), "=r"(b3) : "r"(baddr[P]));
            MMA16816F(acc[2 * P],     a0, a1, a2, a3, b0, b1);
            MMA16816F(acc[2 * P + 1], a0, a1, a2, a3, b2, b3);
        }
        __syncthreads();
    }

    // write partials
    int row = rq * 16 + (lane >> 2);
    int colb = cw * 32 + (lane & 3) * 2;
    float* outp = Ppart + (size_t)ks * 64 * N;
#pragma unroll
    for (int nt = 0; nt < 4; nt++) {
#pragma unroll
        for (int pr = 0; pr < 2; pr++) {
            int r = row + pr * 8;
            int c = n0 + colb + nt * 8;
            if (c < N)     outp[(size_t)r * N + c]     = acc[nt][pr * 2 + 0];
            if (c + 1 < N) outp[(size_t)r * N + c + 1] = acc[nt][pr * 2 + 1];
        }
    }
}

// ---------------- FC: scalar K-split GEMM partials (FC4) + reduce ----------------
__global__ __launch_bounds__(256)
void gemm_part(const float* __restrict__ X, const float* __restrict__ W,
               float* __restrict__ Ppart, int N, int K, int KS)
{
    int n0 = blockIdx.x * 64;
    int ks = blockIdx.y;
    int k0s = (int)(((long)K * ks) / KS);
    int k1s = (int)(((long)K * (ks + 1)) / KS);

    __shared__ float Asm[64][17];
    __shared__ float Bsm[16][65];

    int tid = threadIdx.x;
    int nl  = tid & 63;
    int mg  = tid >> 6;

    bool vec_ok = ((N & 3) == 0);

    float acc[16];
#pragma unroll
    for (int i = 0; i < 16; i++) acc[i] = 0.f;

    for (int k0 = k0s; k0 < k1s; k0 += 16) {
#pragma unroll
        for (int i = 0; i < 4; i++) {
            int rr = (tid >> 4) + i * 16;
            int cc = tid & 15;
            int k = k0 + cc;
            Asm[rr][cc] = (k < k1s) ? X[(size_t)rr * K + k] : 0.f;
        }
        {
            int rr = tid >> 4;
            int c4 = (tid & 15) * 4;
            int k  = k0 + rr;
            int nn = n0 + c4;
            if (vec_ok && k < k1s && nn + 3 < N) {
                float4 v = *(const float4*)&W[(size_t)k * N + nn];
                Bsm[rr][c4]     = v.x;
                Bsm[rr][c4 + 1] = v.y;
                Bsm[rr][c4 + 2] = v.z;
                Bsm[rr][c4 + 3] = v.w;
            } else {
#pragma unroll
                for (int e = 0; e < 4; e++)
                    Bsm[rr][c4 + e] = (k < k1s && nn + e < N)
                                      ? W[(size_t)k * N + nn + e] : 0.f;
            }
        }
        __syncthreads();
#pragma unroll
        for (int kk = 0; kk < 16; kk++) {
            float bv = Bsm[kk][nl];
#pragma unroll
            for (int i = 0; i < 16; i++)
                acc[i] += Asm[mg * 16 + i][kk] * bv;
        }
        __syncthreads();
    }

    int nn = n0 + nl;
    if (nn < N) {
        float* outp = Ppart + (size_t)ks * 64 * N;
#pragma unroll
        for (int i = 0; i < 16; i++)
            outp[(size_t)(mg * 16 + i) * N + nn] = acc[i];
    }
}

__global__ void reduce_bias(const float* __restrict__ Ppart, const float* __restrict__ bias,
                            float* __restrict__ Y, int N, int KS)
{
    int idx = blockIdx.x * 256 + threadIdx.x;
    if (idx >= 64 * N) return;
    int nn = idx % N;
    float s = bias[nn];
    for (int ks = 0; ks < KS; ks++) s += Ppart[(size_t)ks * 64 * N + idx];
    Y[idx] = s;
}

// ---------------- launch ----------------
extern "C" void kernel_launch(void* const* d_in, const int* in_sizes, int n_in,
                              void* d_out, int out_size)
{
    const float* x1  = (const float*)d_in[0];
    const float* x2  = (const float*)d_in[1];
    const float* wx1 = (const float*)d_in[2];
    const float* wh1 = (const float*)d_in[3];
    const float* bx1 = (const float*)d_in[4];
    const float* bh1 = (const float*)d_in[5];
    const float* wx2 = (const float*)d_in[6];
    const float* wh2 = (const float*)d_in[7];
    const float* bx2 = (const float*)d_in[8];
    const float* bh2 = (const float*)d_in[9];
    const float* fw2 = (const float*)d_in[10];
    const float* fb2 = (const float*)d_in[11];
    const float* fw3 = (const float*)d_in[12];
    const float* fb3 = (const float*)d_in[13];
    const float* fw4 = (const float*)d_in[14];
    const float* fb4 = (const float*)d_in[15];
    const float* fw5 = (const float*)d_in[16];
    const float* fb5 = (const float*)d_in[17];

    float *feat, *y1, *y2, *y3, *part;
    cudaGetSymbolAddress((void**)&feat, g_feat);
    cudaGetSymbolAddress((void**)&y1,   g_y1);
    cudaGetSymbolAddress((void**)&y2,   g_y2);
    cudaGetSymbolAddress((void**)&y3,   g_y3);
    cudaGetSymbolAddress((void**)&part, g_part);

    cudaFuncSetAttribute(lstm_mma, cudaFuncAttributeMaxDynamicSharedMemorySize, SMEM_BYTES);

    lstm_mma<<<440, 256, SMEM_BYTES>>>(x1, x2, wx1, wh1, bx1, bh1,
                                       wx2, wh2, bx2, bh2, feat);

    // FC1: 7040 -> 3400  (fp16 HMMA, KS=16, grid 54x16)
    gemm16_part<<<dim3(54, 16), 256>>>(feat, fw2, part, 3400, 7040, 16);
    reduce_bias<<<(64 * 3400 + 255) / 256, 256>>>(part, fb2, y1, 3400, 16);
    // FC2: 3400 -> 1000  (fp16 HMMA, KS=32, grid 16x32)
    gemm16_part<<<dim3(16, 32), 256>>>(y1, fw3, part, 1000, 3400, 32);
    reduce_bias<<<(64 * 1000 + 255) / 256, 256>>>(part, fb3, y2, 1000, 32);
    // FC3: 1000 -> 500   (fp16 HMMA, KS=32, grid 8x32)
    gemm16_part<<<dim3(8, 32), 256>>>(y2, fw4, part, 500, 1000, 32);
    reduce_bias<<<(64 * 500 + 255) / 256, 256>>>(part, fb4, y3, 500, 32);
    // FC4: 500 -> 50     (scalar fp32, KS=8)
    gemm_part<<<dim3(1, 8), 256>>>(y3, fw5, part, 50, 500, 8);
    reduce_bias<<<(64 * 50 + 255) / 256, 256>>>(part, fb5, (float*)d_out, 50, 8);
}